// round 2
// baseline (speedup 1.0000x reference)
#include <cuda_runtime.h>
#include <math.h>

// ---------------------------------------------------------------------------
// Problem constants
// ---------------------------------------------------------------------------
#define BATCH 8
#define SEQ 1024
#define DMODEL 1024
#define NHEAD 16
#define HDIM 64
#define DFF 4096
#define NTOK (BATCH * SEQ)          // 8192 rows

// ---------------------------------------------------------------------------
// Scratch buffers (device globals: allocation-free)
// ---------------------------------------------------------------------------
__device__ float g_xn1[NTOK * DMODEL];
__device__ float g_q  [NTOK * DMODEL];
__device__ float g_k  [NTOK * DMODEL];
__device__ float g_v  [NTOK * DMODEL];
__device__ float g_att[NTOK * DMODEL];
__device__ float g_x2 [NTOK * DMODEL];
__device__ float g_xn2[NTOK * DMODEL];
__device__ float g_h  [NTOK * DFF];
__device__ float g_wqc[DMODEL * DMODEL];
__device__ float g_wkc[DMODEL * DMODEL];
__device__ float g_wvc[DMODEL * DMODEL];

// ---------------------------------------------------------------------------
// LayerNorm: one block per row of 1024
// ---------------------------------------------------------------------------
__global__ void ln_kernel(const float* __restrict__ x, const float* __restrict__ g,
                          const float* __restrict__ b, float* __restrict__ y) {
    int row = blockIdx.x;
    int tid = threadIdx.x;
    const float* xr = x + (size_t)row * DMODEL;
    float*       yr = y + (size_t)row * DMODEL;

    float v[4];
    float s = 0.f, s2 = 0.f;
#pragma unroll
    for (int i = 0; i < 4; i++) {
        v[i] = xr[tid + 256 * i];
        s  += v[i];
        s2 += v[i] * v[i];
    }
#pragma unroll
    for (int o = 16; o; o >>= 1) {
        s  += __shfl_xor_sync(0xffffffffu, s,  o);
        s2 += __shfl_xor_sync(0xffffffffu, s2, o);
    }
    __shared__ float ss[8], ss2[8];
    int w = tid >> 5, lane = tid & 31;
    if (lane == 0) { ss[w] = s; ss2[w] = s2; }
    __syncthreads();
    s = 0.f; s2 = 0.f;
#pragma unroll
    for (int i = 0; i < 8; i++) { s += ss[i]; s2 += ss2[i]; }

    float mean = s * (1.f / DMODEL);
    float var  = s2 * (1.f / DMODEL) - mean * mean;
    float rstd = rsqrtf(var + 1e-5f);
#pragma unroll
    for (int i = 0; i < 4; i++) {
        int c = tid + 256 * i;
        yr[c] = (v[i] - mean) * rstd * g[c] + b[c];
    }
}

// ---------------------------------------------------------------------------
// Repack (H, D, E) -> (D, H*E) row-major
// ---------------------------------------------------------------------------
__global__ void repack_w(const float* __restrict__ w, float* __restrict__ wc) {
    int idx = blockIdx.x * 256 + threadIdx.x;   // over DMODEL*DMODEL
    int d = idx >> 10;
    int n = idx & 1023;
    int h = n >> 6;
    int e = n & 63;
    wc[idx] = w[(h << 16) + (d << 6) + e];      // h*D*E + d*E + e
}

// ---------------------------------------------------------------------------
// SGEMM 128x128x8, 256 threads, 8x8 micro-tile
// EPI bits: 1 = +bias[col], 2 = relu, 4 = +res[row,col]
// ---------------------------------------------------------------------------
template <int EPI>
__global__ void gemm_k(const float* __restrict__ A, const float* __restrict__ B,
                       const float* __restrict__ bias, const float* __restrict__ res,
                       float* __restrict__ C, int M, int N, int K) {
    __shared__ float As[8][128];
    __shared__ float Bs[8][128];

    int bx = blockIdx.x;          // N tile
    int by = blockIdx.y;          // M tile
    int tid = threadIdx.x;
    int tx = tid & 15;            // 0..15
    int ty = tid >> 4;            // 0..15

    int aRow = tid >> 1;          // 0..127
    int aCol = (tid & 1) * 4;     // 0 or 4
    int bRow = tid >> 5;          // 0..7
    int bCol = (tid & 31) * 4;    // 0..124

    const float* Ap = A + (size_t)(by * 128 + aRow) * K + aCol;
    const float* Bp = B + (size_t)bRow * N + bx * 128 + bCol;

    float acc[8][8];
#pragma unroll
    for (int i = 0; i < 8; i++)
#pragma unroll
        for (int j = 0; j < 8; j++) acc[i][j] = 0.f;

    for (int k0 = 0; k0 < K; k0 += 8) {
        float4 a4 = *(const float4*)(Ap + k0);
        As[aCol + 0][aRow] = a4.x;
        As[aCol + 1][aRow] = a4.y;
        As[aCol + 2][aRow] = a4.z;
        As[aCol + 3][aRow] = a4.w;
        float4 b4 = *(const float4*)(Bp + (size_t)k0 * N);
        *(float4*)&Bs[bRow][bCol] = b4;
        __syncthreads();

#pragma unroll
        for (int kk = 0; kk < 8; kk++) {
            float ar[8], br[8];
#pragma unroll
            for (int i = 0; i < 8; i++) ar[i] = As[kk][ty * 8 + i];
#pragma unroll
            for (int j = 0; j < 8; j++) br[j] = Bs[kk][tx * 8 + j];
#pragma unroll
            for (int i = 0; i < 8; i++)
#pragma unroll
                for (int j = 0; j < 8; j++) acc[i][j] += ar[i] * br[j];
        }
        __syncthreads();
    }

#pragma unroll
    for (int i = 0; i < 8; i++) {
        int row = by * 128 + ty * 8 + i;
#pragma unroll
        for (int j = 0; j < 8; j++) {
            int col = bx * 128 + tx * 8 + j;
            float val = acc[i][j];
            if (EPI & 1) val += bias[col];
            if (EPI & 2) val = fmaxf(val, 0.f);
            if (EPI & 4) val += res[(size_t)row * N + col];
            C[(size_t)row * N + col] = val;
        }
    }
}

// ---------------------------------------------------------------------------
// Causal flash attention.
// Q/K/V layout: [B, T, H*E] (head h occupies columns h*64..h*64+63).
// Grid: (T/64, B*H). Block: 256 threads. BM=64 query rows, BN=32 key rows.
// Each row handled by 4 threads (tid>>2 = row, tid&3 = quarter).
// ---------------------------------------------------------------------------
#define BM 64
#define BN 32

__global__ void attn_kernel(const float* __restrict__ Q, const float* __restrict__ K,
                            const float* __restrict__ V, float* __restrict__ O) {
    int qb = blockIdx.x;
    int bh = blockIdx.y;
    int b  = bh >> 4;
    int h  = bh & 15;

    const size_t base = (size_t)b * SEQ * DMODEL + (size_t)h * HDIM;

    __shared__ float ks[BN][HDIM];   // 8 KB
    __shared__ float vs[BN][HDIM];   // 8 KB
    __shared__ float ps[BM][BN];     // 8 KB

    int tid = threadIdx.x;
    int r   = tid >> 2;              // 0..63 query row in tile
    int jg  = tid & 3;               // quarter index
    int iglob = qb * BM + r;

    // Q row in registers (4 threads per row load the same row — cheap, L1/L2 hit)
    float4 qr[16];
    {
        const float4* qrow = (const float4*)(Q + base + (size_t)iglob * DMODEL);
#pragma unroll
        for (int i = 0; i < 16; i++) qr[i] = qrow[i];
    }

    float m = -1e30f, l = 0.f;
    float acc[16];
#pragma unroll
    for (int i = 0; i < 16; i++) acc[i] = 0.f;

    const float scale = 0.125f;      // 1/sqrt(64)
    int nkb = (qb * BM + BM + BN - 1) / BN;   // 2*qb + 2

    for (int kb = 0; kb < nkb; kb++) {
        // load K/V tiles (all 256 threads)
#pragma unroll
        for (int it = 0; it < 2; it++) {
            int i  = tid + it * 256;          // 0..511 -> BN*16 float4
            int rr = i >> 4;
            int c4 = (i & 15) * 4;
            *(float4*)&ks[rr][c4] = *(const float4*)&K[base + (size_t)(kb * BN + rr) * DMODEL + c4];
            *(float4*)&vs[rr][c4] = *(const float4*)&V[base + (size_t)(kb * BN + rr) * DMODEL + c4];
        }
        __syncthreads();

        // warp-uniform skip: warp covers rows [(tid>>5)*8, +8)
        int warp_max_row = qb * BM + ((tid >> 5) << 3) + 7;
        if (kb * BN <= warp_max_row) {
            float s[8];
#pragma unroll
            for (int j = 0; j < 8; j++) {
                const float4* kro = (const float4*)&ks[jg * 8 + j][0];
                float d0 = 0.f, d1 = 0.f;
#pragma unroll
                for (int c = 0; c < 16; c += 2) {
                    float4 k4 = kro[c];
                    d0 += qr[c].x * k4.x + qr[c].y * k4.y + qr[c].z * k4.z + qr[c].w * k4.w;
                    float4 k5 = kro[c + 1];
                    d1 += qr[c+1].x * k5.x + qr[c+1].y * k5.y + qr[c+1].z * k5.z + qr[c+1].w * k5.w;
                }
                s[j] = d0 + d1;
            }

            float smax = -1e30f;
#pragma unroll
            for (int j = 0; j < 8; j++) {
                int jglob = kb * BN + jg * 8 + j;
                s[j] = (jglob <= iglob) ? s[j] * scale : -1e30f;
                smax = fmaxf(smax, s[j]);
            }
            smax = fmaxf(smax, __shfl_xor_sync(0xffffffffu, smax, 1));
            smax = fmaxf(smax, __shfl_xor_sync(0xffffffffu, smax, 2));

            float mnew = fmaxf(m, smax);
            float corr = __expf(m - mnew);
            float lsum = 0.f;
#pragma unroll
            for (int j = 0; j < 8; j++) {
                float p = __expf(s[j] - mnew);
                ps[r][jg * 8 + j] = p;
                lsum += p;
            }
            lsum += __shfl_xor_sync(0xffffffffu, lsum, 1);
            lsum += __shfl_xor_sync(0xffffffffu, lsum, 2);
            l = l * corr + lsum;
            m = mnew;
#pragma unroll
            for (int i = 0; i < 16; i++) acc[i] *= corr;
            __syncwarp();

            // O += P @ V  (thread owns output cols jg*16 .. +16)
#pragma unroll 4
            for (int j = 0; j < BN; j++) {
                float p = ps[r][j];
                const float4* vro = (const float4*)&vs[j][jg * 16];
#pragma unroll
                for (int c = 0; c < 4; c++) {
                    float4 v4 = vro[c];
                    acc[c * 4 + 0] += p * v4.x;
                    acc[c * 4 + 1] += p * v4.y;
                    acc[c * 4 + 2] += p * v4.z;
                    acc[c * 4 + 3] += p * v4.w;
                }
            }
        }
        __syncthreads();
    }

    float inv = 1.f / l;
    float* orow = (float*)(O + base + (size_t)iglob * DMODEL + jg * 16);
#pragma unroll
    for (int c = 0; c < 4; c++) {
        float4 o4;
        o4.x = acc[c * 4 + 0] * inv;
        o4.y = acc[c * 4 + 1] * inv;
        o4.z = acc[c * 4 + 2] * inv;
        o4.w = acc[c * 4 + 3] * inv;
        *(float4*)(orow + c * 4) = o4;
    }
}

// ---------------------------------------------------------------------------
// Launch
// ---------------------------------------------------------------------------
extern "C" void kernel_launch(void* const* d_in, const int* in_sizes, int n_in,
                              void* d_out, int out_size) {
    const float* x      = (const float*)d_in[0];
    const float* wq     = (const float*)d_in[1];
    const float* wk     = (const float*)d_in[2];
    const float* wv     = (const float*)d_in[3];
    const float* w_proj = (const float*)d_in[4];
    const float* b_proj = (const float*)d_in[5];
    const float* w1     = (const float*)d_in[6];
    const float* b1     = (const float*)d_in[7];
    const float* w2     = (const float*)d_in[8];
    const float* b2     = (const float*)d_in[9];
    const float* g1     = (const float*)d_in[10];
    const float* be1    = (const float*)d_in[11];
    const float* g2     = (const float*)d_in[12];
    const float* be2    = (const float*)d_in[13];
    float* out = (float*)d_out;

    float *xn1, *q, *k, *v, *att, *x2, *xn2, *hb, *wqc, *wkc, *wvc;
    cudaGetSymbolAddress((void**)&xn1, g_xn1);
    cudaGetSymbolAddress((void**)&q,   g_q);
    cudaGetSymbolAddress((void**)&k,   g_k);
    cudaGetSymbolAddress((void**)&v,   g_v);
    cudaGetSymbolAddress((void**)&att, g_att);
    cudaGetSymbolAddress((void**)&x2,  g_x2);
    cudaGetSymbolAddress((void**)&xn2, g_xn2);
    cudaGetSymbolAddress((void**)&hb,  g_h);
    cudaGetSymbolAddress((void**)&wqc, g_wqc);
    cudaGetSymbolAddress((void**)&wkc, g_wkc);
    cudaGetSymbolAddress((void**)&wvc, g_wvc);

    // 1. LN1
    ln_kernel<<<NTOK, 256>>>(x, g1, be1, xn1);

    // 2. repack per-head weights to (D, H*E)
    repack_w<<<(DMODEL * DMODEL) / 256, 256>>>(wq, wqc);
    repack_w<<<(DMODEL * DMODEL) / 256, 256>>>(wk, wkc);
    repack_w<<<(DMODEL * DMODEL) / 256, 256>>>(wv, wvc);

    // 3. QKV projections
    dim3 gproj(DMODEL / 128, NTOK / 128);
    gemm_k<0><<<gproj, 256>>>(xn1, wqc, nullptr, nullptr, q, NTOK, DMODEL, DMODEL);
    gemm_k<0><<<gproj, 256>>>(xn1, wkc, nullptr, nullptr, k, NTOK, DMODEL, DMODEL);
    gemm_k<0><<<gproj, 256>>>(xn1, wvc, nullptr, nullptr, v, NTOK, DMODEL, DMODEL);

    // 4. attention
    attn_kernel<<<dim3(SEQ / BM, BATCH * NHEAD), 256>>>(q, k, v, att);

    // 5. output projection + bias + residual(xn1)
    gemm_k<5><<<gproj, 256>>>(att, w_proj, b_proj, xn1, x2, NTOK, DMODEL, DMODEL);

    // 6. LN2
    ln_kernel<<<NTOK, 256>>>(x2, g2, be2, xn2);

    // 7. FFN up + bias + relu
    gemm_k<3><<<dim3(DFF / 128, NTOK / 128), 256>>>(xn2, w1, b1, nullptr, hb, NTOK, DFF, DMODEL);

    // 8. FFN down + bias + residual(xn2) -> out
    gemm_k<5><<<gproj, 256>>>(hb, w2, b2, xn2, out, NTOK, DMODEL, DFF);
}

// round 3
// speedup vs baseline: 1.6817x; 1.6817x over previous
#include <cuda_runtime.h>
#include <math.h>

// ---------------------------------------------------------------------------
// Problem constants
// ---------------------------------------------------------------------------
#define BATCH 8
#define SEQ 1024
#define DMODEL 1024
#define NHEAD 16
#define HDIM 64
#define DFF 4096
#define NTOK (BATCH * SEQ)          // 8192 rows

// ---------------------------------------------------------------------------
// Scratch buffers (device globals: allocation-free)
// ---------------------------------------------------------------------------
__device__ float g_xn1[NTOK * DMODEL];
__device__ float g_q  [NTOK * DMODEL];
__device__ float g_k  [NTOK * DMODEL];
__device__ float g_v  [NTOK * DMODEL];
__device__ float g_att[NTOK * DMODEL];
__device__ float g_x2 [NTOK * DMODEL];
__device__ float g_xn2[NTOK * DMODEL];
__device__ float g_h  [NTOK * DFF];
__device__ float g_wqc[DMODEL * DMODEL];
__device__ float g_wkc[DMODEL * DMODEL];
__device__ float g_wvc[DMODEL * DMODEL];

// ---------------------------------------------------------------------------
// LayerNorm: one block per row of 1024
// ---------------------------------------------------------------------------
__global__ void ln_kernel(const float* __restrict__ x, const float* __restrict__ g,
                          const float* __restrict__ b, float* __restrict__ y) {
    int row = blockIdx.x;
    int tid = threadIdx.x;
    const float* xr = x + (size_t)row * DMODEL;
    float*       yr = y + (size_t)row * DMODEL;

    float v[4];
    float s = 0.f, s2 = 0.f;
#pragma unroll
    for (int i = 0; i < 4; i++) {
        v[i] = xr[tid + 256 * i];
        s  += v[i];
        s2 += v[i] * v[i];
    }
#pragma unroll
    for (int o = 16; o; o >>= 1) {
        s  += __shfl_xor_sync(0xffffffffu, s,  o);
        s2 += __shfl_xor_sync(0xffffffffu, s2, o);
    }
    __shared__ float ss[8], ss2[8];
    int w = tid >> 5, lane = tid & 31;
    if (lane == 0) { ss[w] = s; ss2[w] = s2; }
    __syncthreads();
    s = 0.f; s2 = 0.f;
#pragma unroll
    for (int i = 0; i < 8; i++) { s += ss[i]; s2 += ss2[i]; }

    float mean = s * (1.f / DMODEL);
    float var  = s2 * (1.f / DMODEL) - mean * mean;
    float rstd = rsqrtf(var + 1e-5f);
#pragma unroll
    for (int i = 0; i < 4; i++) {
        int c = tid + 256 * i;
        yr[c] = (v[i] - mean) * rstd * g[c] + b[c];
    }
}

// ---------------------------------------------------------------------------
// Repack (H, D, E) -> (D, H*E) row-major
// ---------------------------------------------------------------------------
__global__ void repack_w(const float* __restrict__ w, float* __restrict__ wc) {
    int idx = blockIdx.x * 256 + threadIdx.x;   // over DMODEL*DMODEL
    int d = idx >> 10;
    int n = idx & 1023;
    int h = n >> 6;
    int e = n & 63;
    wc[idx] = w[(h << 16) + (d << 6) + e];      // h*D*E + d*E + e
}

// ---------------------------------------------------------------------------
// TF32 tensor-core GEMM: C[M,N] = A[M,K] @ B[K,N]
// 128x128x16 tiles, 256 threads, warp grid 2(m) x 4(n), warp tile 64x32,
// mma.sync.aligned.m16n8k8.row.col.f32.tf32.tf32.f32, 4x4 mma tiles per warp.
// Double-buffered SMEM, pad +8 so fragment LDS is bank-conflict-free.
// EPI bits: 1 = +bias[col], 2 = relu, 4 = +res[row,col]
// ---------------------------------------------------------------------------
__device__ __forceinline__ unsigned f2tf(float x) {
    unsigned r;
    asm("cvt.rna.tf32.f32 %0, %1;" : "=r"(r) : "f"(x));
    return r;
}

__device__ __forceinline__ void mma_tf32(float* d, const unsigned* a, const unsigned* b) {
    asm volatile(
        "mma.sync.aligned.m16n8k8.row.col.f32.tf32.tf32.f32 "
        "{%0,%1,%2,%3}, {%4,%5,%6,%7}, {%8,%9}, {%0,%1,%2,%3};\n"
        : "+f"(d[0]), "+f"(d[1]), "+f"(d[2]), "+f"(d[3])
        : "r"(a[0]), "r"(a[1]), "r"(a[2]), "r"(a[3]), "r"(b[0]), "r"(b[1]));
}

#define TBM 128
#define TBN 128
#define TBK 16
#define SPAD 8

template <int EPI>
__global__ __launch_bounds__(256, 2)
void gemm_tf32(const float* __restrict__ A, const float* __restrict__ B,
               const float* __restrict__ bias, const float* __restrict__ res,
               float* __restrict__ C, int M, int N, int K) {
    __shared__ float As[2][TBK][TBM + SPAD];
    __shared__ float Bs[2][TBK][TBN + SPAD];

    const int t   = threadIdx.x;
    const int bx  = blockIdx.x;
    const int by  = blockIdx.y;

    // global-load indexing
    const int aRow = t >> 2;              // 0..63
    const int aK   = (t & 3) * 4;         // 0,4,8,12
    const int bK   = t >> 5;              // 0..7
    const int bN   = (t & 31) * 4;        // 0..124

    const float* Ap0 = A + (size_t)(by * TBM + aRow) * K + aK;
    const float* Ap1 = Ap0 + (size_t)64 * K;
    const float* Bp0 = B + (size_t)bK * N + bx * TBN + bN;
    const float* Bp1 = Bp0 + (size_t)8 * N;

    // compute indexing
    const int lane = t & 31;
    const int warp = t >> 5;
    const int wm   = warp & 1;            // 2 warps along M
    const int wn   = warp >> 1;           // 4 warps along N
    const int m0   = wm * 64;
    const int n0   = wn * 32;
    const int g    = lane >> 2;           // 0..7
    const int tig  = lane & 3;            // 0..3

    float acc[4][4][4];
#pragma unroll
    for (int mi = 0; mi < 4; mi++)
#pragma unroll
        for (int ni = 0; ni < 4; ni++)
#pragma unroll
            for (int r = 0; r < 4; r++) acc[mi][ni][r] = 0.f;

    // ---- preload tile 0 ----
    {
        float4 a0 = *(const float4*)Ap0;
        float4 a1 = *(const float4*)Ap1;
        float4 b0 = *(const float4*)Bp0;
        float4 b1 = *(const float4*)Bp1;
        As[0][aK + 0][aRow]      = __uint_as_float(f2tf(a0.x));
        As[0][aK + 1][aRow]      = __uint_as_float(f2tf(a0.y));
        As[0][aK + 2][aRow]      = __uint_as_float(f2tf(a0.z));
        As[0][aK + 3][aRow]      = __uint_as_float(f2tf(a0.w));
        As[0][aK + 0][aRow + 64] = __uint_as_float(f2tf(a1.x));
        As[0][aK + 1][aRow + 64] = __uint_as_float(f2tf(a1.y));
        As[0][aK + 2][aRow + 64] = __uint_as_float(f2tf(a1.z));
        As[0][aK + 3][aRow + 64] = __uint_as_float(f2tf(a1.w));
        float4 c0, c1;
        c0.x = __uint_as_float(f2tf(b0.x)); c0.y = __uint_as_float(f2tf(b0.y));
        c0.z = __uint_as_float(f2tf(b0.z)); c0.w = __uint_as_float(f2tf(b0.w));
        c1.x = __uint_as_float(f2tf(b1.x)); c1.y = __uint_as_float(f2tf(b1.y));
        c1.z = __uint_as_float(f2tf(b1.z)); c1.w = __uint_as_float(f2tf(b1.w));
        *(float4*)&Bs[0][bK][bN]     = c0;
        *(float4*)&Bs[0][bK + 8][bN] = c1;
    }
    __syncthreads();

    const int nTiles = K / TBK;
    for (int tt = 0; tt < nTiles; tt++) {
        const int buf = tt & 1;

        // prefetch next tile into registers
        float4 pa0, pa1, pb0, pb1;
        const bool hasNext = (tt + 1) < nTiles;
        if (hasNext) {
            int k0 = (tt + 1) * TBK;
            pa0 = *(const float4*)(Ap0 + k0);
            pa1 = *(const float4*)(Ap1 + k0);
            pb0 = *(const float4*)(Bp0 + (size_t)k0 * N);
            pb1 = *(const float4*)(Bp1 + (size_t)k0 * N);
        }

        // compute current tile
#pragma unroll
        for (int kk = 0; kk < TBK; kk += 8) {
            unsigned af[4][4];
#pragma unroll
            for (int mi = 0; mi < 4; mi++) {
                int m = m0 + mi * 16 + g;
                af[mi][0] = __float_as_uint(As[buf][kk + tig    ][m]);
                af[mi][1] = __float_as_uint(As[buf][kk + tig    ][m + 8]);
                af[mi][2] = __float_as_uint(As[buf][kk + tig + 4][m]);
                af[mi][3] = __float_as_uint(As[buf][kk + tig + 4][m + 8]);
            }
            unsigned bf[4][2];
#pragma unroll
            for (int ni = 0; ni < 4; ni++) {
                int n = n0 + ni * 8 + g;
                bf[ni][0] = __float_as_uint(Bs[buf][kk + tig    ][n]);
                bf[ni][1] = __float_as_uint(Bs[buf][kk + tig + 4][n]);
            }
#pragma unroll
            for (int mi = 0; mi < 4; mi++)
#pragma unroll
                for (int ni = 0; ni < 4; ni++)
                    mma_tf32(acc[mi][ni], af[mi], bf[ni]);
        }

        // store prefetched into other buffer
        if (hasNext) {
            const int nb = buf ^ 1;
            As[nb][aK + 0][aRow]      = __uint_as_float(f2tf(pa0.x));
            As[nb][aK + 1][aRow]      = __uint_as_float(f2tf(pa0.y));
            As[nb][aK + 2][aRow]      = __uint_as_float(f2tf(pa0.z));
            As[nb][aK + 3][aRow]      = __uint_as_float(f2tf(pa0.w));
            As[nb][aK + 0][aRow + 64] = __uint_as_float(f2tf(pa1.x));
            As[nb][aK + 1][aRow + 64] = __uint_as_float(f2tf(pa1.y));
            As[nb][aK + 2][aRow + 64] = __uint_as_float(f2tf(pa1.z));
            As[nb][aK + 3][aRow + 64] = __uint_as_float(f2tf(pa1.w));
            float4 c0, c1;
            c0.x = __uint_as_float(f2tf(pb0.x)); c0.y = __uint_as_float(f2tf(pb0.y));
            c0.z = __uint_as_float(f2tf(pb0.z)); c0.w = __uint_as_float(f2tf(pb0.w));
            c1.x = __uint_as_float(f2tf(pb1.x)); c1.y = __uint_as_float(f2tf(pb1.y));
            c1.z = __uint_as_float(f2tf(pb1.z)); c1.w = __uint_as_float(f2tf(pb1.w));
            *(float4*)&Bs[nb][bK][bN]     = c0;
            *(float4*)&Bs[nb][bK + 8][bN] = c1;
        }
        __syncthreads();
    }

    // ---- epilogue ----
#pragma unroll
    for (int mi = 0; mi < 4; mi++) {
#pragma unroll
        for (int ni = 0; ni < 4; ni++) {
            int row = by * TBM + m0 + mi * 16 + g;
            int col = bx * TBN + n0 + ni * 8 + tig * 2;
            float v0 = acc[mi][ni][0];
            float v1 = acc[mi][ni][1];
            float v2 = acc[mi][ni][2];
            float v3 = acc[mi][ni][3];
            if (EPI & 1) {
                float bb0 = bias[col], bb1 = bias[col + 1];
                v0 += bb0; v1 += bb1; v2 += bb0; v3 += bb1;
            }
            if (EPI & 2) {
                v0 = fmaxf(v0, 0.f); v1 = fmaxf(v1, 0.f);
                v2 = fmaxf(v2, 0.f); v3 = fmaxf(v3, 0.f);
            }
            if (EPI & 4) {
                const float* r0 = res + (size_t)row * N + col;
                const float* r1 = r0 + (size_t)8 * N;
                v0 += r0[0]; v1 += r0[1]; v2 += r1[0]; v3 += r1[1];
            }
            float2 o0 = make_float2(v0, v1);
            float2 o1 = make_float2(v2, v3);
            *(float2*)(C + (size_t)row * N + col)       = o0;
            *(float2*)(C + (size_t)(row + 8) * N + col) = o1;
        }
    }
}

// ---------------------------------------------------------------------------
// Causal flash attention (fp32, unchanged from R1)
// ---------------------------------------------------------------------------
#define BM 64
#define BN 32

__global__ void attn_kernel(const float* __restrict__ Q, const float* __restrict__ K,
                            const float* __restrict__ V, float* __restrict__ O) {
    int qb = blockIdx.x;
    int bh = blockIdx.y;
    int b  = bh >> 4;
    int h  = bh & 15;

    const size_t base = (size_t)b * SEQ * DMODEL + (size_t)h * HDIM;

    __shared__ float ks[BN][HDIM];
    __shared__ float vs[BN][HDIM];
    __shared__ float ps[BM][BN];

    int tid = threadIdx.x;
    int r   = tid >> 2;
    int jg  = tid & 3;
    int iglob = qb * BM + r;

    float4 qr[16];
    {
        const float4* qrow = (const float4*)(Q + base + (size_t)iglob * DMODEL);
#pragma unroll
        for (int i = 0; i < 16; i++) qr[i] = qrow[i];
    }

    float m = -1e30f, l = 0.f;
    float acc[16];
#pragma unroll
    for (int i = 0; i < 16; i++) acc[i] = 0.f;

    const float scale = 0.125f;
    int nkb = (qb * BM + BM + BN - 1) / BN;

    for (int kb = 0; kb < nkb; kb++) {
#pragma unroll
        for (int it = 0; it < 2; it++) {
            int i  = tid + it * 256;
            int rr = i >> 4;
            int c4 = (i & 15) * 4;
            *(float4*)&ks[rr][c4] = *(const float4*)&K[base + (size_t)(kb * BN + rr) * DMODEL + c4];
            *(float4*)&vs[rr][c4] = *(const float4*)&V[base + (size_t)(kb * BN + rr) * DMODEL + c4];
        }
        __syncthreads();

        int warp_max_row = qb * BM + ((tid >> 5) << 3) + 7;
        if (kb * BN <= warp_max_row) {
            float s[8];
#pragma unroll
            for (int j = 0; j < 8; j++) {
                const float4* kro = (const float4*)&ks[jg * 8 + j][0];
                float d0 = 0.f, d1 = 0.f;
#pragma unroll
                for (int c = 0; c < 16; c += 2) {
                    float4 k4 = kro[c];
                    d0 += qr[c].x * k4.x + qr[c].y * k4.y + qr[c].z * k4.z + qr[c].w * k4.w;
                    float4 k5 = kro[c + 1];
                    d1 += qr[c+1].x * k5.x + qr[c+1].y * k5.y + qr[c+1].z * k5.z + qr[c+1].w * k5.w;
                }
                s[j] = d0 + d1;
            }

            float smax = -1e30f;
#pragma unroll
            for (int j = 0; j < 8; j++) {
                int jglob = kb * BN + jg * 8 + j;
                s[j] = (jglob <= iglob) ? s[j] * scale : -1e30f;
                smax = fmaxf(smax, s[j]);
            }
            smax = fmaxf(smax, __shfl_xor_sync(0xffffffffu, smax, 1));
            smax = fmaxf(smax, __shfl_xor_sync(0xffffffffu, smax, 2));

            float mnew = fmaxf(m, smax);
            float corr = __expf(m - mnew);
            float lsum = 0.f;
#pragma unroll
            for (int j = 0; j < 8; j++) {
                float p = __expf(s[j] - mnew);
                ps[r][jg * 8 + j] = p;
                lsum += p;
            }
            lsum += __shfl_xor_sync(0xffffffffu, lsum, 1);
            lsum += __shfl_xor_sync(0xffffffffu, lsum, 2);
            l = l * corr + lsum;
            m = mnew;
#pragma unroll
            for (int i = 0; i < 16; i++) acc[i] *= corr;
            __syncwarp();

#pragma unroll 4
            for (int j = 0; j < BN; j++) {
                float p = ps[r][j];
                const float4* vro = (const float4*)&vs[j][jg * 16];
#pragma unroll
                for (int c = 0; c < 4; c++) {
                    float4 v4 = vro[c];
                    acc[c * 4 + 0] += p * v4.x;
                    acc[c * 4 + 1] += p * v4.y;
                    acc[c * 4 + 2] += p * v4.z;
                    acc[c * 4 + 3] += p * v4.w;
                }
            }
        }
        __syncthreads();
    }

    float inv = 1.f / l;
    float* orow = (float*)(O + base + (size_t)iglob * DMODEL + jg * 16);
#pragma unroll
    for (int c = 0; c < 4; c++) {
        float4 o4;
        o4.x = acc[c * 4 + 0] * inv;
        o4.y = acc[c * 4 + 1] * inv;
        o4.z = acc[c * 4 + 2] * inv;
        o4.w = acc[c * 4 + 3] * inv;
        *(float4*)(orow + c * 4) = o4;
    }
}

// ---------------------------------------------------------------------------
// Launch
// ---------------------------------------------------------------------------
extern "C" void kernel_launch(void* const* d_in, const int* in_sizes, int n_in,
                              void* d_out, int out_size) {
    const float* x      = (const float*)d_in[0];
    const float* wq     = (const float*)d_in[1];
    const float* wk     = (const float*)d_in[2];
    const float* wv     = (const float*)d_in[3];
    const float* w_proj = (const float*)d_in[4];
    const float* b_proj = (const float*)d_in[5];
    const float* w1     = (const float*)d_in[6];
    const float* b1     = (const float*)d_in[7];
    const float* w2     = (const float*)d_in[8];
    const float* b2     = (const float*)d_in[9];
    const float* g1     = (const float*)d_in[10];
    const float* be1    = (const float*)d_in[11];
    const float* g2     = (const float*)d_in[12];
    const float* be2    = (const float*)d_in[13];
    float* out = (float*)d_out;

    float *xn1, *q, *k, *v, *att, *x2, *xn2, *hb, *wqc, *wkc, *wvc;
    cudaGetSymbolAddress((void**)&xn1, g_xn1);
    cudaGetSymbolAddress((void**)&q,   g_q);
    cudaGetSymbolAddress((void**)&k,   g_k);
    cudaGetSymbolAddress((void**)&v,   g_v);
    cudaGetSymbolAddress((void**)&att, g_att);
    cudaGetSymbolAddress((void**)&x2,  g_x2);
    cudaGetSymbolAddress((void**)&xn2, g_xn2);
    cudaGetSymbolAddress((void**)&hb,  g_h);
    cudaGetSymbolAddress((void**)&wqc, g_wqc);
    cudaGetSymbolAddress((void**)&wkc, g_wkc);
    cudaGetSymbolAddress((void**)&wvc, g_wvc);

    // 1. LN1
    ln_kernel<<<NTOK, 256>>>(x, g1, be1, xn1);

    // 2. repack per-head weights to (D, H*E)
    repack_w<<<(DMODEL * DMODEL) / 256, 256>>>(wq, wqc);
    repack_w<<<(DMODEL * DMODEL) / 256, 256>>>(wk, wkc);
    repack_w<<<(DMODEL * DMODEL) / 256, 256>>>(wv, wvc);

    // 3. QKV projections (tf32 tensor cores)
    dim3 gproj(DMODEL / TBN, NTOK / TBM);
    gemm_tf32<0><<<gproj, 256>>>(xn1, wqc, nullptr, nullptr, q, NTOK, DMODEL, DMODEL);
    gemm_tf32<0><<<gproj, 256>>>(xn1, wkc, nullptr, nullptr, k, NTOK, DMODEL, DMODEL);
    gemm_tf32<0><<<gproj, 256>>>(xn1, wvc, nullptr, nullptr, v, NTOK, DMODEL, DMODEL);

    // 4. attention
    attn_kernel<<<dim3(SEQ / BM, BATCH * NHEAD), 256>>>(q, k, v, att);

    // 5. output projection + bias + residual(xn1)
    gemm_tf32<5><<<gproj, 256>>>(att, w_proj, b_proj, xn1, x2, NTOK, DMODEL, DMODEL);

    // 6. LN2
    ln_kernel<<<NTOK, 256>>>(x2, g2, be2, xn2);

    // 7. FFN up + bias + relu
    gemm_tf32<3><<<dim3(DFF / TBN, NTOK / TBM), 256>>>(xn2, w1, b1, nullptr, hb, NTOK, DFF, DMODEL);

    // 8. FFN down + bias + residual(xn2) -> out
    gemm_tf32<5><<<gproj, 256>>>(hb, w2, b2, xn2, out, NTOK, DMODEL, DFF);
}

// round 5
// speedup vs baseline: 4.2212x; 2.5101x over previous
#include <cuda_runtime.h>
#include <math.h>

// ---------------------------------------------------------------------------
// Problem constants
// ---------------------------------------------------------------------------
#define BATCH 8
#define SEQ 1024
#define DMODEL 1024
#define NHEAD 16
#define HDIM 64
#define DFF 4096
#define NTOK (BATCH * SEQ)          // 8192 rows

// ---------------------------------------------------------------------------
// Scratch buffers (device globals: allocation-free)
// ---------------------------------------------------------------------------
__device__ float g_xn1[NTOK * DMODEL];
__device__ float g_q  [NTOK * DMODEL];
__device__ float g_k  [NTOK * DMODEL];
__device__ float g_v  [NTOK * DMODEL];
__device__ float g_att[NTOK * DMODEL];
__device__ float g_x2 [NTOK * DMODEL];
__device__ float g_xn2[NTOK * DMODEL];
__device__ float g_h  [NTOK * DFF];
__device__ float g_wqc[DMODEL * DMODEL];
__device__ float g_wkc[DMODEL * DMODEL];
__device__ float g_wvc[DMODEL * DMODEL];

// ---------------------------------------------------------------------------
// tf32 helpers
// ---------------------------------------------------------------------------
__device__ __forceinline__ unsigned f2tf(float x) {
    unsigned r;
    asm("cvt.rna.tf32.f32 %0, %1;" : "=r"(r) : "f"(x));
    return r;
}

__device__ __forceinline__ void mma_tf32(float* d, const unsigned* a, const unsigned* b) {
    asm volatile(
        "mma.sync.aligned.m16n8k8.row.col.f32.tf32.tf32.f32 "
        "{%0,%1,%2,%3}, {%4,%5,%6,%7}, {%8,%9}, {%0,%1,%2,%3};\n"
        : "+f"(d[0]), "+f"(d[1]), "+f"(d[2]), "+f"(d[3])
        : "r"(a[0]), "r"(a[1]), "r"(a[2]), "r"(a[3]), "r"(b[0]), "r"(b[1]));
}

// ---------------------------------------------------------------------------
// LayerNorm: one block per row of 1024
// ---------------------------------------------------------------------------
__global__ void ln_kernel(const float* __restrict__ x, const float* __restrict__ g,
                          const float* __restrict__ b, float* __restrict__ y) {
    int row = blockIdx.x;
    int tid = threadIdx.x;
    const float* xr = x + (size_t)row * DMODEL;
    float*       yr = y + (size_t)row * DMODEL;

    float v[4];
    float s = 0.f, s2 = 0.f;
#pragma unroll
    for (int i = 0; i < 4; i++) {
        v[i] = xr[tid + 256 * i];
        s  += v[i];
        s2 += v[i] * v[i];
    }
#pragma unroll
    for (int o = 16; o; o >>= 1) {
        s  += __shfl_xor_sync(0xffffffffu, s,  o);
        s2 += __shfl_xor_sync(0xffffffffu, s2, o);
    }
    __shared__ float ss[8], ss2[8];
    int w = tid >> 5, lane = tid & 31;
    if (lane == 0) { ss[w] = s; ss2[w] = s2; }
    __syncthreads();
    s = 0.f; s2 = 0.f;
#pragma unroll
    for (int i = 0; i < 8; i++) { s += ss[i]; s2 += ss2[i]; }

    float mean = s * (1.f / DMODEL);
    float var  = s2 * (1.f / DMODEL) - mean * mean;
    float rstd = rsqrtf(var + 1e-5f);
#pragma unroll
    for (int i = 0; i < 4; i++) {
        int c = tid + 256 * i;
        yr[c] = (v[i] - mean) * rstd * g[c] + b[c];
    }
}

// ---------------------------------------------------------------------------
// Repack (H, D, E) -> (D, H*E) row-major
// ---------------------------------------------------------------------------
__global__ void repack_w(const float* __restrict__ w, float* __restrict__ wc) {
    int idx = blockIdx.x * 256 + threadIdx.x;   // over DMODEL*DMODEL
    int d = idx >> 10;
    int n = idx & 1023;
    int h = n >> 6;
    int e = n & 63;
    wc[idx] = w[(h << 16) + (d << 6) + e];      // h*D*E + d*E + e
}

// ---------------------------------------------------------------------------
// TF32 tensor-core GEMM (unchanged from R2): C[M,N] = A[M,K] @ B[K,N]
// EPI bits: 1 = +bias[col], 2 = relu, 4 = +res[row,col]
// ---------------------------------------------------------------------------
#define TBM 128
#define TBN 128
#define TBK 16
#define SPAD 8

template <int EPI>
__global__ __launch_bounds__(256, 2)
void gemm_tf32(const float* __restrict__ A, const float* __restrict__ B,
               const float* __restrict__ bias, const float* __restrict__ res,
               float* __restrict__ C, int M, int N, int K) {
    __shared__ float As[2][TBK][TBM + SPAD];
    __shared__ float Bs[2][TBK][TBN + SPAD];

    const int t   = threadIdx.x;
    const int bx  = blockIdx.x;
    const int by  = blockIdx.y;

    const int aRow = t >> 2;
    const int aK   = (t & 3) * 4;
    const int bK   = t >> 5;
    const int bN   = (t & 31) * 4;

    const float* Ap0 = A + (size_t)(by * TBM + aRow) * K + aK;
    const float* Ap1 = Ap0 + (size_t)64 * K;
    const float* Bp0 = B + (size_t)bK * N + bx * TBN + bN;
    const float* Bp1 = Bp0 + (size_t)8 * N;

    const int lane = t & 31;
    const int warp = t >> 5;
    const int wm   = warp & 1;
    const int wn   = warp >> 1;
    const int m0   = wm * 64;
    const int n0   = wn * 32;
    const int g    = lane >> 2;
    const int tig  = lane & 3;

    float acc[4][4][4];
#pragma unroll
    for (int mi = 0; mi < 4; mi++)
#pragma unroll
        for (int ni = 0; ni < 4; ni++)
#pragma unroll
            for (int r = 0; r < 4; r++) acc[mi][ni][r] = 0.f;

    {
        float4 a0 = *(const float4*)Ap0;
        float4 a1 = *(const float4*)Ap1;
        float4 b0 = *(const float4*)Bp0;
        float4 b1 = *(const float4*)Bp1;
        As[0][aK + 0][aRow]      = __uint_as_float(f2tf(a0.x));
        As[0][aK + 1][aRow]      = __uint_as_float(f2tf(a0.y));
        As[0][aK + 2][aRow]      = __uint_as_float(f2tf(a0.z));
        As[0][aK + 3][aRow]      = __uint_as_float(f2tf(a0.w));
        As[0][aK + 0][aRow + 64] = __uint_as_float(f2tf(a1.x));
        As[0][aK + 1][aRow + 64] = __uint_as_float(f2tf(a1.y));
        As[0][aK + 2][aRow + 64] = __uint_as_float(f2tf(a1.z));
        As[0][aK + 3][aRow + 64] = __uint_as_float(f2tf(a1.w));
        float4 c0, c1;
        c0.x = __uint_as_float(f2tf(b0.x)); c0.y = __uint_as_float(f2tf(b0.y));
        c0.z = __uint_as_float(f2tf(b0.z)); c0.w = __uint_as_float(f2tf(b0.w));
        c1.x = __uint_as_float(f2tf(b1.x)); c1.y = __uint_as_float(f2tf(b1.y));
        c1.z = __uint_as_float(f2tf(b1.z)); c1.w = __uint_as_float(f2tf(b1.w));
        *(float4*)&Bs[0][bK][bN]     = c0;
        *(float4*)&Bs[0][bK + 8][bN] = c1;
    }
    __syncthreads();

    const int nTiles = K / TBK;
    for (int tt = 0; tt < nTiles; tt++) {
        const int buf = tt & 1;

        float4 pa0, pa1, pb0, pb1;
        const bool hasNext = (tt + 1) < nTiles;
        if (hasNext) {
            int k0 = (tt + 1) * TBK;
            pa0 = *(const float4*)(Ap0 + k0);
            pa1 = *(const float4*)(Ap1 + k0);
            pb0 = *(const float4*)(Bp0 + (size_t)k0 * N);
            pb1 = *(const float4*)(Bp1 + (size_t)k0 * N);
        }

#pragma unroll
        for (int kk = 0; kk < TBK; kk += 8) {
            unsigned af[4][4];
#pragma unroll
            for (int mi = 0; mi < 4; mi++) {
                int m = m0 + mi * 16 + g;
                af[mi][0] = __float_as_uint(As[buf][kk + tig    ][m]);
                af[mi][1] = __float_as_uint(As[buf][kk + tig    ][m + 8]);
                af[mi][2] = __float_as_uint(As[buf][kk + tig + 4][m]);
                af[mi][3] = __float_as_uint(As[buf][kk + tig + 4][m + 8]);
            }
            unsigned bf[4][2];
#pragma unroll
            for (int ni = 0; ni < 4; ni++) {
                int n = n0 + ni * 8 + g;
                bf[ni][0] = __float_as_uint(Bs[buf][kk + tig    ][n]);
                bf[ni][1] = __float_as_uint(Bs[buf][kk + tig + 4][n]);
            }
#pragma unroll
            for (int mi = 0; mi < 4; mi++)
#pragma unroll
                for (int ni = 0; ni < 4; ni++)
                    mma_tf32(acc[mi][ni], af[mi], bf[ni]);
        }

        if (hasNext) {
            const int nb = buf ^ 1;
            As[nb][aK + 0][aRow]      = __uint_as_float(f2tf(pa0.x));
            As[nb][aK + 1][aRow]      = __uint_as_float(f2tf(pa0.y));
            As[nb][aK + 2][aRow]      = __uint_as_float(f2tf(pa0.z));
            As[nb][aK + 3][aRow]      = __uint_as_float(f2tf(pa0.w));
            As[nb][aK + 0][aRow + 64] = __uint_as_float(f2tf(pa1.x));
            As[nb][aK + 1][aRow + 64] = __uint_as_float(f2tf(pa1.y));
            As[nb][aK + 2][aRow + 64] = __uint_as_float(f2tf(pa1.z));
            As[nb][aK + 3][aRow + 64] = __uint_as_float(f2tf(pa1.w));
            float4 c0, c1;
            c0.x = __uint_as_float(f2tf(pb0.x)); c0.y = __uint_as_float(f2tf(pb0.y));
            c0.z = __uint_as_float(f2tf(pb0.z)); c0.w = __uint_as_float(f2tf(pb0.w));
            c1.x = __uint_as_float(f2tf(pb1.x)); c1.y = __uint_as_float(f2tf(pb1.y));
            c1.z = __uint_as_float(f2tf(pb1.z)); c1.w = __uint_as_float(f2tf(pb1.w));
            *(float4*)&Bs[nb][bK][bN]     = c0;
            *(float4*)&Bs[nb][bK + 8][bN] = c1;
        }
        __syncthreads();
    }

#pragma unroll
    for (int mi = 0; mi < 4; mi++) {
#pragma unroll
        for (int ni = 0; ni < 4; ni++) {
            int row = by * TBM + m0 + mi * 16 + g;
            int col = bx * TBN + n0 + ni * 8 + tig * 2;
            float v0 = acc[mi][ni][0];
            float v1 = acc[mi][ni][1];
            float v2 = acc[mi][ni][2];
            float v3 = acc[mi][ni][3];
            if (EPI & 1) {
                float bb0 = bias[col], bb1 = bias[col + 1];
                v0 += bb0; v1 += bb1; v2 += bb0; v3 += bb1;
            }
            if (EPI & 2) {
                v0 = fmaxf(v0, 0.f); v1 = fmaxf(v1, 0.f);
                v2 = fmaxf(v2, 0.f); v3 = fmaxf(v3, 0.f);
            }
            if (EPI & 4) {
                const float* r0 = res + (size_t)row * N + col;
                const float* r1 = r0 + (size_t)8 * N;
                v0 += r0[0]; v1 += r0[1]; v2 += r1[0]; v3 += r1[1];
            }
            *(float2*)(C + (size_t)row * N + col)       = make_float2(v0, v1);
            *(float2*)(C + (size_t)(row + 8) * N + col) = make_float2(v2, v3);
        }
    }
}

// ---------------------------------------------------------------------------
// Tensor-core causal flash attention (tf32 mma).
// Block = 128 threads (4 warps), handles 64 query rows of one (b,h).
// Warp w owns q rows [w*16, w*16+16). KV tiles of 64.
// SMEM strides chosen for conflict-free fragment loads:
//   Ks stride 68: b-frag bank = (g*4+tig)        -> 32 distinct
//   Vs stride 72: b-frag bank = (tig*8+g)        -> 32 distinct
//   Ps stride 68: a-frag bank = (g*4+tig)        -> 32 distinct
// ---------------------------------------------------------------------------
#define KS_S 68
#define VS_S 72
#define PS_S 68

__global__ __launch_bounds__(128)
void attn_mma(const float* __restrict__ Q, const float* __restrict__ K,
              const float* __restrict__ V, float* __restrict__ O) {
    __shared__ __align__(16) float Ks[64][KS_S];
    __shared__ __align__(16) float Vs[64][VS_S];
    __shared__ __align__(16) float Ps[64][PS_S];

    const int qb = blockIdx.x;
    const int bh = blockIdx.y;
    const int b  = bh >> 4;
    const int h  = bh & 15;
    const size_t base = (size_t)b * SEQ * DMODEL + (size_t)h * HDIM;

    const int tid  = threadIdx.x;
    const int warp = tid >> 5;
    const int lane = tid & 31;
    const int g    = lane >> 2;
    const int tig  = lane & 3;
    const int m    = warp * 16;          // warp's q-row offset in tile
    const int q0   = qb * 64;

    // ---- stage Q tile into Ps, then extract A-fragments (tf32) ----
#pragma unroll
    for (int it = 0; it < 8; it++) {
        int i  = it * 128 + tid;         // 1024 float4
        int rr = i >> 4;
        int c4 = (i & 15) * 4;
        float4 qv = *(const float4*)&Q[base + (size_t)(q0 + rr) * DMODEL + c4];
        Ps[rr][c4 + 0] = qv.x; Ps[rr][c4 + 1] = qv.y;
        Ps[rr][c4 + 2] = qv.z; Ps[rr][c4 + 3] = qv.w;
    }
    __syncthreads();

    unsigned qf[8][4];
#pragma unroll
    for (int kk = 0; kk < 8; kk++) {
        qf[kk][0] = f2tf(Ps[m + g    ][kk * 8 + tig    ]);
        qf[kk][1] = f2tf(Ps[m + g + 8][kk * 8 + tig    ]);
        qf[kk][2] = f2tf(Ps[m + g    ][kk * 8 + tig + 4]);
        qf[kk][3] = f2tf(Ps[m + g + 8][kk * 8 + tig + 4]);
    }

    float o[8][4];
#pragma unroll
    for (int ni = 0; ni < 8; ni++)
#pragma unroll
        for (int r = 0; r < 4; r++) o[ni][r] = 0.f;
    float mrun0 = -1e30f, mrun1 = -1e30f, lrun0 = 0.f, lrun1 = 0.f;

    const float scale = 0.125f;          // 1/sqrt(64)
    const int row0 = q0 + m + g;
    const int row1 = row0 + 8;

    for (int kb = 0; kb <= qb; kb++) {
        __syncthreads();                 // previous Ks/Vs reads done
        // ---- load K,V tiles (convert to tf32 bits at load) ----
#pragma unroll
        for (int it = 0; it < 8; it++) {
            int i  = it * 128 + tid;
            int rr = i >> 4;
            int c4 = (i & 15) * 4;
            const float* kp = &K[base + (size_t)(kb * 64 + rr) * DMODEL + c4];
            const float* vp = &V[base + (size_t)(kb * 64 + rr) * DMODEL + c4];
            float4 kv = *(const float4*)kp;
            float4 vv = *(const float4*)vp;
            Ks[rr][c4 + 0] = __uint_as_float(f2tf(kv.x));
            Ks[rr][c4 + 1] = __uint_as_float(f2tf(kv.y));
            Ks[rr][c4 + 2] = __uint_as_float(f2tf(kv.z));
            Ks[rr][c4 + 3] = __uint_as_float(f2tf(kv.w));
            Vs[rr][c4 + 0] = __uint_as_float(f2tf(vv.x));
            Vs[rr][c4 + 1] = __uint_as_float(f2tf(vv.y));
            Vs[rr][c4 + 2] = __uint_as_float(f2tf(vv.z));
            Vs[rr][c4 + 3] = __uint_as_float(f2tf(vv.w));
        }
        __syncthreads();

        // ---- S = Q @ K^T ----
        float s[8][4];
#pragma unroll
        for (int ni = 0; ni < 8; ni++)
#pragma unroll
            for (int r = 0; r < 4; r++) s[ni][r] = 0.f;
#pragma unroll
        for (int kk = 0; kk < 8; kk++) {
#pragma unroll
            for (int ni = 0; ni < 8; ni++) {
                unsigned bf[2];
                bf[0] = __float_as_uint(Ks[ni * 8 + g][kk * 8 + tig    ]);
                bf[1] = __float_as_uint(Ks[ni * 8 + g][kk * 8 + tig + 4]);
                mma_tf32(s[ni], qf[kk], bf);
            }
        }

        // ---- scale + causal mask ----
        if (kb == qb) {
#pragma unroll
            for (int ni = 0; ni < 8; ni++) {
                int c0 = kb * 64 + ni * 8 + tig * 2;
                int c1 = c0 + 1;
                s[ni][0] = (c0 <= row0) ? s[ni][0] * scale : -1e30f;
                s[ni][1] = (c1 <= row0) ? s[ni][1] * scale : -1e30f;
                s[ni][2] = (c0 <= row1) ? s[ni][2] * scale : -1e30f;
                s[ni][3] = (c1 <= row1) ? s[ni][3] * scale : -1e30f;
            }
        } else {
#pragma unroll
            for (int ni = 0; ni < 8; ni++) {
                s[ni][0] *= scale; s[ni][1] *= scale;
                s[ni][2] *= scale; s[ni][3] *= scale;
            }
        }

        // ---- online softmax ----
        float mx0 = -1e30f, mx1 = -1e30f;
#pragma unroll
        for (int ni = 0; ni < 8; ni++) {
            mx0 = fmaxf(mx0, fmaxf(s[ni][0], s[ni][1]));
            mx1 = fmaxf(mx1, fmaxf(s[ni][2], s[ni][3]));
        }
        mx0 = fmaxf(mx0, __shfl_xor_sync(0xffffffffu, mx0, 1));
        mx0 = fmaxf(mx0, __shfl_xor_sync(0xffffffffu, mx0, 2));
        mx1 = fmaxf(mx1, __shfl_xor_sync(0xffffffffu, mx1, 1));
        mx1 = fmaxf(mx1, __shfl_xor_sync(0xffffffffu, mx1, 2));

        float mnew0 = fmaxf(mrun0, mx0);
        float mnew1 = fmaxf(mrun1, mx1);
        float corr0 = __expf(mrun0 - mnew0);
        float corr1 = __expf(mrun1 - mnew1);

        float ls0 = 0.f, ls1 = 0.f;
#pragma unroll
        for (int ni = 0; ni < 8; ni++) {
            float p0 = __expf(s[ni][0] - mnew0);
            float p1 = __expf(s[ni][1] - mnew0);
            float p2 = __expf(s[ni][2] - mnew1);
            float p3 = __expf(s[ni][3] - mnew1);
            ls0 += p0 + p1;
            ls1 += p2 + p3;
            int c = ni * 8 + tig * 2;
            Ps[m + g    ][c    ] = __uint_as_float(f2tf(p0));
            Ps[m + g    ][c + 1] = __uint_as_float(f2tf(p1));
            Ps[m + g + 8][c    ] = __uint_as_float(f2tf(p2));
            Ps[m + g + 8][c + 1] = __uint_as_float(f2tf(p3));
        }
        ls0 += __shfl_xor_sync(0xffffffffu, ls0, 1);
        ls0 += __shfl_xor_sync(0xffffffffu, ls0, 2);
        ls1 += __shfl_xor_sync(0xffffffffu, ls1, 1);
        ls1 += __shfl_xor_sync(0xffffffffu, ls1, 2);

        lrun0 = lrun0 * corr0 + ls0;
        lrun1 = lrun1 * corr1 + ls1;
        mrun0 = mnew0;
        mrun1 = mnew1;
#pragma unroll
        for (int ni = 0; ni < 8; ni++) {
            o[ni][0] *= corr0; o[ni][1] *= corr0;
            o[ni][2] *= corr1; o[ni][3] *= corr1;
        }
        __syncwarp();

        // ---- O += P @ V ----
#pragma unroll
        for (int kk = 0; kk < 8; kk++) {
            unsigned pf[4];
            pf[0] = __float_as_uint(Ps[m + g    ][kk * 8 + tig    ]);
            pf[1] = __float_as_uint(Ps[m + g + 8][kk * 8 + tig    ]);
            pf[2] = __float_as_uint(Ps[m + g    ][kk * 8 + tig + 4]);
            pf[3] = __float_as_uint(Ps[m + g + 8][kk * 8 + tig + 4]);
#pragma unroll
            for (int ni = 0; ni < 8; ni++) {
                unsigned vb[2];
                vb[0] = __float_as_uint(Vs[kk * 8 + tig    ][ni * 8 + g]);
                vb[1] = __float_as_uint(Vs[kk * 8 + tig + 4][ni * 8 + g]);
                mma_tf32(o[ni], pf, vb);
            }
        }
    }

    // ---- epilogue ----
    float inv0 = 1.f / lrun0;
    float inv1 = 1.f / lrun1;
#pragma unroll
    for (int ni = 0; ni < 8; ni++) {
        int col = ni * 8 + tig * 2;
        *(float2*)&O[base + (size_t)row0 * DMODEL + col] =
            make_float2(o[ni][0] * inv0, o[ni][1] * inv0);
        *(float2*)&O[base + (size_t)row1 * DMODEL + col] =
            make_float2(o[ni][2] * inv1, o[ni][3] * inv1);
    }
}

// ---------------------------------------------------------------------------
// Launch
// ---------------------------------------------------------------------------
extern "C" void kernel_launch(void* const* d_in, const int* in_sizes, int n_in,
                              void* d_out, int out_size) {
    const float* x      = (const float*)d_in[0];
    const float* wq     = (const float*)d_in[1];
    const float* wk     = (const float*)d_in[2];
    const float* wv     = (const float*)d_in[3];
    const float* w_proj = (const float*)d_in[4];
    const float* b_proj = (const float*)d_in[5];
    const float* w1     = (const float*)d_in[6];
    const float* b1     = (const float*)d_in[7];
    const float* w2     = (const float*)d_in[8];
    const float* b2     = (const float*)d_in[9];
    const float* g1     = (const float*)d_in[10];
    const float* be1    = (const float*)d_in[11];
    const float* g2     = (const float*)d_in[12];
    const float* be2    = (const float*)d_in[13];
    float* out = (float*)d_out;

    float *xn1, *q, *k, *v, *att, *x2, *xn2, *hb, *wqc, *wkc, *wvc;
    cudaGetSymbolAddress((void**)&xn1, g_xn1);
    cudaGetSymbolAddress((void**)&q,   g_q);
    cudaGetSymbolAddress((void**)&k,   g_k);
    cudaGetSymbolAddress((void**)&v,   g_v);
    cudaGetSymbolAddress((void**)&att, g_att);
    cudaGetSymbolAddress((void**)&x2,  g_x2);
    cudaGetSymbolAddress((void**)&xn2, g_xn2);
    cudaGetSymbolAddress((void**)&hb,  g_h);
    cudaGetSymbolAddress((void**)&wqc, g_wqc);
    cudaGetSymbolAddress((void**)&wkc, g_wkc);
    cudaGetSymbolAddress((void**)&wvc, g_wvc);

    // 1. LN1
    ln_kernel<<<NTOK, 256>>>(x, g1, be1, xn1);

    // 2. repack per-head weights to (D, H*E)
    repack_w<<<(DMODEL * DMODEL) / 256, 256>>>(wq, wqc);
    repack_w<<<(DMODEL * DMODEL) / 256, 256>>>(wk, wkc);
    repack_w<<<(DMODEL * DMODEL) / 256, 256>>>(wv, wvc);

    // 3. QKV projections (tf32 tensor cores)
    dim3 gproj(DMODEL / TBN, NTOK / TBM);
    gemm_tf32<0><<<gproj, 256>>>(xn1, wqc, nullptr, nullptr, q, NTOK, DMODEL, DMODEL);
    gemm_tf32<0><<<gproj, 256>>>(xn1, wkc, nullptr, nullptr, k, NTOK, DMODEL, DMODEL);
    gemm_tf32<0><<<gproj, 256>>>(xn1, wvc, nullptr, nullptr, v, NTOK, DMODEL, DMODEL);

    // 4. attention (tf32 tensor cores)
    attn_mma<<<dim3(SEQ / 64, BATCH * NHEAD), 128>>>(q, k, v, att);

    // 5. output projection + bias + residual(xn1)
    gemm_tf32<5><<<gproj, 256>>>(att, w_proj, b_proj, xn1, x2, NTOK, DMODEL, DMODEL);

    // 6. LN2
    ln_kernel<<<NTOK, 256>>>(x2, g2, be2, xn2);

    // 7. FFN up + bias + relu
    gemm_tf32<3><<<dim3(DFF / TBN, NTOK / TBM), 256>>>(xn2, w1, b1, nullptr, hb, NTOK, DFF, DMODEL);

    // 8. FFN down + bias + residual(xn2) -> out
    gemm_tf32<5><<<gproj, 256>>>(hb, w2, b2, xn2, out, NTOK, DMODEL, DFF);
}

// round 9
// speedup vs baseline: 4.6478x; 1.1011x over previous
#include <cuda_runtime.h>
#include <math.h>

// ---------------------------------------------------------------------------
// Problem constants
// ---------------------------------------------------------------------------
#define BATCH 8
#define SEQ 1024
#define DMODEL 1024
#define NHEAD 16
#define HDIM 64
#define DFF 4096
#define NTOK (BATCH * SEQ)          // 8192 rows
#define QKV3 (3 * DMODEL)           // 3072

// ---------------------------------------------------------------------------
// Scratch buffers (device globals: allocation-free)
// ---------------------------------------------------------------------------
__device__ float g_xn1 [NTOK * DMODEL];
__device__ float g_qkv [NTOK * QKV3];
__device__ float g_att [NTOK * DMODEL];
__device__ float g_x2  [NTOK * DMODEL];
__device__ float g_xn2 [NTOK * DMODEL];
__device__ float g_h   [NTOK * DFF];
__device__ float g_wqkv[DMODEL * QKV3];

// ---------------------------------------------------------------------------
// tf32 helpers
// ---------------------------------------------------------------------------
__device__ __forceinline__ unsigned f2tf(float x) {
    unsigned r;
    asm("cvt.rna.tf32.f32 %0, %1;" : "=r"(r) : "f"(x));
    return r;
}

__device__ __forceinline__ void mma_tf32(float* d, const unsigned* a, const unsigned* b) {
    asm volatile(
        "mma.sync.aligned.m16n8k8.row.col.f32.tf32.tf32.f32 "
        "{%0,%1,%2,%3}, {%4,%5,%6,%7}, {%8,%9}, {%0,%1,%2,%3};\n"
        : "+f"(d[0]), "+f"(d[1]), "+f"(d[2]), "+f"(d[3])
        : "r"(a[0]), "r"(a[1]), "r"(a[2]), "r"(a[3]), "r"(b[0]), "r"(b[1]));
}

__device__ __forceinline__ void cpasync16(unsigned dst, const void* src) {
    asm volatile("cp.async.cg.shared.global [%0], [%1], 16;\n" :: "r"(dst), "l"(src));
}
#define CP_COMMIT() asm volatile("cp.async.commit_group;\n" ::: "memory")
#define CP_WAIT1()  asm volatile("cp.async.wait_group 1;\n" ::: "memory")

// ---------------------------------------------------------------------------
// LayerNorm: one block per row of 1024
// ---------------------------------------------------------------------------
__global__ void ln_kernel(const float* __restrict__ x, const float* __restrict__ g,
                          const float* __restrict__ b, float* __restrict__ y) {
    int row = blockIdx.x;
    int tid = threadIdx.x;
    const float* xr = x + (size_t)row * DMODEL;
    float*       yr = y + (size_t)row * DMODEL;

    float v[4];
    float s = 0.f, s2 = 0.f;
#pragma unroll
    for (int i = 0; i < 4; i++) {
        v[i] = xr[tid + 256 * i];
        s  += v[i];
        s2 += v[i] * v[i];
    }
#pragma unroll
    for (int o = 16; o; o >>= 1) {
        s  += __shfl_xor_sync(0xffffffffu, s,  o);
        s2 += __shfl_xor_sync(0xffffffffu, s2, o);
    }
    __shared__ float ss[8], ss2[8];
    int w = tid >> 5, lane = tid & 31;
    if (lane == 0) { ss[w] = s; ss2[w] = s2; }
    __syncthreads();
    s = 0.f; s2 = 0.f;
#pragma unroll
    for (int i = 0; i < 8; i++) { s += ss[i]; s2 += ss2[i]; }

    float mean = s * (1.f / DMODEL);
    float var  = s2 * (1.f / DMODEL) - mean * mean;
    float rstd = rsqrtf(var + 1e-5f);
#pragma unroll
    for (int i = 0; i < 4; i++) {
        int c = tid + 256 * i;
        yr[c] = (v[i] - mean) * rstd * g[c] + b[c];
    }
}

// ---------------------------------------------------------------------------
// Repack (H, D, E) -> rows D, packed QKV columns (stride 3072)
// ---------------------------------------------------------------------------
__global__ void repack_w(const float* __restrict__ w, float* __restrict__ wc) {
    int idx = blockIdx.x * 256 + threadIdx.x;   // over DMODEL*DMODEL
    int d = idx >> 10;
    int n = idx & 1023;
    int h = n >> 6;
    int e = n & 63;
    wc[(size_t)d * QKV3 + n] = w[(h << 16) + (d << 6) + e];   // h*D*E + d*E + e
}

// ---------------------------------------------------------------------------
// TF32 tensor-core GEMM with 3-stage cp.async pipeline.
// C[M,N] = A[M,K] @ B[K,N].  128x128x16 tiles, 256 threads,
// warp grid 2(m) x 4(n), warp tile 64x32, raw-fp32 operands (HW truncates).
// SMEM (dynamic): A stages [128][20], B stages [16][132].
//   a-frag banks: g*20+tig (mod 32) distinct; b-frag banks: tig*4+g distinct.
// EPI bits: 1 = +bias[col], 2 = relu, 4 = +res[row,col]
// ---------------------------------------------------------------------------
#define STAGES 3
#define AS_S 20
#define BS_S 132
#define AS_ELEMS (128 * AS_S)        // 2560
#define BS_ELEMS (16 * BS_S)         // 2112
#define B_BASE (STAGES * AS_ELEMS)   // 7680
#define GEMM_SMEM_BYTES ((B_BASE + STAGES * BS_ELEMS) * 4)  // 56064

template <int EPI>
__global__ __launch_bounds__(256, 2)
void gemm_cp(const float* __restrict__ A, const float* __restrict__ B,
             const float* __restrict__ bias, const float* __restrict__ res,
             float* __restrict__ C, int M, int N, int K) {
    extern __shared__ float sm[];
    const unsigned sbase = (unsigned)__cvta_generic_to_shared(sm);

    const int t  = threadIdx.x;
    const int bx = blockIdx.x;
    const int by = blockIdx.y;

    const int lane = t & 31;
    const int warp = t >> 5;
    const int wm   = warp & 1;
    const int wn   = warp >> 1;
    const int m0   = wm * 64;
    const int n0   = wn * 32;
    const int g    = lane >> 2;
    const int tig  = lane & 3;

    // load indexing (two 16B chunks per thread per matrix)
    const int ar0 = t >> 2,            ac0 = (t & 3) * 4;          // chunk t
    const int ar1 = (t + 256) >> 2,    ac1 = ((t + 256) & 3) * 4;  // chunk t+256
    const int br0 = t >> 5,            bc0 = (t & 31) * 4;
    const int br1 = (t + 256) >> 5,    bc1 = ((t + 256) & 31) * 4;

    const float* Abase = A + (size_t)(by * 128) * K;
    const float* Bbase = B + bx * 128;

    float acc[4][4][4];
#pragma unroll
    for (int mi = 0; mi < 4; mi++)
#pragma unroll
        for (int ni = 0; ni < 4; ni++)
#pragma unroll
            for (int r = 0; r < 4; r++) acc[mi][ni][r] = 0.f;

    const int nTiles = K / 16;

    // issue a stage's loads
    auto issue = [&](int st, int k0) {
        unsigned abase = sbase + (st * AS_ELEMS) * 4;
        unsigned bbase = sbase + (B_BASE + st * BS_ELEMS) * 4;
        cpasync16(abase + (ar0 * AS_S + ac0) * 4, Abase + (size_t)ar0 * K + k0 + ac0);
        cpasync16(abase + (ar1 * AS_S + ac1) * 4, Abase + (size_t)ar1 * K + k0 + ac1);
        cpasync16(bbase + (br0 * BS_S + bc0) * 4, Bbase + (size_t)(k0 + br0) * N + bc0);
        cpasync16(bbase + (br1 * BS_S + bc1) * 4, Bbase + (size_t)(k0 + br1) * N + bc1);
    };

    // prologue: stages 0..STAGES-2
    issue(0, 0);  CP_COMMIT();
    issue(1, 16); CP_COMMIT();
    int lt = 2;

    for (int tt = 0; tt < nTiles; tt++) {
        CP_WAIT1();
        __syncthreads();

        if (lt < nTiles) issue(lt % STAGES, lt * 16);
        CP_COMMIT();
        lt++;

        const int st = tt % STAGES;
        const float* As_ = sm + st * AS_ELEMS;
        const float* Bs_ = sm + B_BASE + st * BS_ELEMS;

#pragma unroll
        for (int kk = 0; kk < 16; kk += 8) {
            unsigned af[4][4];
#pragma unroll
            for (int mi = 0; mi < 4; mi++) {
                int m = m0 + mi * 16 + g;
                af[mi][0] = __float_as_uint(As_[(size_t)m * AS_S + kk + tig]);
                af[mi][1] = __float_as_uint(As_[(size_t)(m + 8) * AS_S + kk + tig]);
                af[mi][2] = __float_as_uint(As_[(size_t)m * AS_S + kk + tig + 4]);
                af[mi][3] = __float_as_uint(As_[(size_t)(m + 8) * AS_S + kk + tig + 4]);
            }
            unsigned bf[4][2];
#pragma unroll
            for (int ni = 0; ni < 4; ni++) {
                int n = n0 + ni * 8 + g;
                bf[ni][0] = __float_as_uint(Bs_[(size_t)(kk + tig) * BS_S + n]);
                bf[ni][1] = __float_as_uint(Bs_[(size_t)(kk + tig + 4) * BS_S + n]);
            }
#pragma unroll
            for (int mi = 0; mi < 4; mi++)
#pragma unroll
                for (int ni = 0; ni < 4; ni++)
                    mma_tf32(acc[mi][ni], af[mi], bf[ni]);
        }
        __syncthreads();
    }

    // ---- epilogue ----
#pragma unroll
    for (int mi = 0; mi < 4; mi++) {
#pragma unroll
        for (int ni = 0; ni < 4; ni++) {
            int row = by * 128 + m0 + mi * 16 + g;
            int col = bx * 128 + n0 + ni * 8 + tig * 2;
            float v0 = acc[mi][ni][0];
            float v1 = acc[mi][ni][1];
            float v2 = acc[mi][ni][2];
            float v3 = acc[mi][ni][3];
            if (EPI & 1) {
                float bb0 = bias[col], bb1 = bias[col + 1];
                v0 += bb0; v1 += bb1; v2 += bb0; v3 += bb1;
            }
            if (EPI & 2) {
                v0 = fmaxf(v0, 0.f); v1 = fmaxf(v1, 0.f);
                v2 = fmaxf(v2, 0.f); v3 = fmaxf(v3, 0.f);
            }
            if (EPI & 4) {
                const float* r0 = res + (size_t)row * N + col;
                const float* r1 = r0 + (size_t)8 * N;
                v0 += r0[0]; v1 += r0[1]; v2 += r1[0]; v3 += r1[1];
            }
            *(float2*)(C + (size_t)row * N + col)       = make_float2(v0, v1);
            *(float2*)(C + (size_t)(row + 8) * N + col) = make_float2(v2, v3);
        }
    }
}

// ---------------------------------------------------------------------------
// Tensor-core causal flash attention (tf32 mma), packed-QKV input (stride 3072).
// Block = 128 threads (4 warps), 64 query rows of one (b,h). KV tiles of 64.
// ---------------------------------------------------------------------------
#define KS_S 68
#define VS_S 72
#define PS_S 68

__global__ __launch_bounds__(128)
void attn_mma(const float* __restrict__ QKV, float* __restrict__ O) {
    __shared__ __align__(16) float Ks[64][KS_S];
    __shared__ __align__(16) float Vs[64][VS_S];
    __shared__ __align__(16) float Ps[64][PS_S];

    const int qb = blockIdx.x;
    const int bh = blockIdx.y;
    const int b  = bh >> 4;
    const int h  = bh & 15;
    const size_t base  = (size_t)b * SEQ * QKV3 + (size_t)h * HDIM;   // Q cols
    const size_t baseO = (size_t)b * SEQ * DMODEL + (size_t)h * HDIM;

    const int tid  = threadIdx.x;
    const int warp = tid >> 5;
    const int lane = tid & 31;
    const int g    = lane >> 2;
    const int tig  = lane & 3;
    const int m    = warp * 16;
    const int q0   = qb * 64;

    // ---- stage Q tile into Ps, then extract A-fragments (tf32) ----
#pragma unroll
    for (int it = 0; it < 8; it++) {
        int i  = it * 128 + tid;
        int rr = i >> 4;
        int c4 = (i & 15) * 4;
        float4 qv = *(const float4*)&QKV[base + (size_t)(q0 + rr) * QKV3 + c4];
        Ps[rr][c4 + 0] = qv.x; Ps[rr][c4 + 1] = qv.y;
        Ps[rr][c4 + 2] = qv.z; Ps[rr][c4 + 3] = qv.w;
    }
    __syncthreads();

    unsigned qf[8][4];
#pragma unroll
    for (int kk = 0; kk < 8; kk++) {
        qf[kk][0] = f2tf(Ps[m + g    ][kk * 8 + tig    ]);
        qf[kk][1] = f2tf(Ps[m + g + 8][kk * 8 + tig    ]);
        qf[kk][2] = f2tf(Ps[m + g    ][kk * 8 + tig + 4]);
        qf[kk][3] = f2tf(Ps[m + g + 8][kk * 8 + tig + 4]);
    }

    float o[8][4];
#pragma unroll
    for (int ni = 0; ni < 8; ni++)
#pragma unroll
        for (int r = 0; r < 4; r++) o[ni][r] = 0.f;
    float mrun0 = -1e30f, mrun1 = -1e30f, lrun0 = 0.f, lrun1 = 0.f;

    const float scale = 0.125f;
    const int row0 = q0 + m + g;
    const int row1 = row0 + 8;

    for (int kb = 0; kb <= qb; kb++) {
        __syncthreads();
#pragma unroll
        for (int it = 0; it < 8; it++) {
            int i  = it * 128 + tid;
            int rr = i >> 4;
            int c4 = (i & 15) * 4;
            size_t roff = base + (size_t)(kb * 64 + rr) * QKV3 + c4;
            float4 kv = *(const float4*)&QKV[roff + DMODEL];       // K block
            float4 vv = *(const float4*)&QKV[roff + 2 * DMODEL];   // V block
            Ks[rr][c4 + 0] = __uint_as_float(f2tf(kv.x));
            Ks[rr][c4 + 1] = __uint_as_float(f2tf(kv.y));
            Ks[rr][c4 + 2] = __uint_as_float(f2tf(kv.z));
            Ks[rr][c4 + 3] = __uint_as_float(f2tf(kv.w));
            Vs[rr][c4 + 0] = __uint_as_float(f2tf(vv.x));
            Vs[rr][c4 + 1] = __uint_as_float(f2tf(vv.y));
            Vs[rr][c4 + 2] = __uint_as_float(f2tf(vv.z));
            Vs[rr][c4 + 3] = __uint_as_float(f2tf(vv.w));
        }
        __syncthreads();

        // ---- S = Q @ K^T ----
        float s[8][4];
#pragma unroll
        for (int ni = 0; ni < 8; ni++)
#pragma unroll
            for (int r = 0; r < 4; r++) s[ni][r] = 0.f;
#pragma unroll
        for (int kk = 0; kk < 8; kk++) {
#pragma unroll
            for (int ni = 0; ni < 8; ni++) {
                unsigned bf[2];
                bf[0] = __float_as_uint(Ks[ni * 8 + g][kk * 8 + tig    ]);
                bf[1] = __float_as_uint(Ks[ni * 8 + g][kk * 8 + tig + 4]);
                mma_tf32(s[ni], qf[kk], bf);
            }
        }

        // ---- scale + causal mask ----
        if (kb == qb) {
#pragma unroll
            for (int ni = 0; ni < 8; ni++) {
                int c0 = kb * 64 + ni * 8 + tig * 2;
                int c1 = c0 + 1;
                s[ni][0] = (c0 <= row0) ? s[ni][0] * scale : -1e30f;
                s[ni][1] = (c1 <= row0) ? s[ni][1] * scale : -1e30f;
                s[ni][2] = (c0 <= row1) ? s[ni][2] * scale : -1e30f;
                s[ni][3] = (c1 <= row1) ? s[ni][3] * scale : -1e30f;
            }
        } else {
#pragma unroll
            for (int ni = 0; ni < 8; ni++) {
                s[ni][0] *= scale; s[ni][1] *= scale;
                s[ni][2] *= scale; s[ni][3] *= scale;
            }
        }

        // ---- online softmax ----
        float mx0 = -1e30f, mx1 = -1e30f;
#pragma unroll
        for (int ni = 0; ni < 8; ni++) {
            mx0 = fmaxf(mx0, fmaxf(s[ni][0], s[ni][1]));
            mx1 = fmaxf(mx1, fmaxf(s[ni][2], s[ni][3]));
        }
        mx0 = fmaxf(mx0, __shfl_xor_sync(0xffffffffu, mx0, 1));
        mx0 = fmaxf(mx0, __shfl_xor_sync(0xffffffffu, mx0, 2));
        mx1 = fmaxf(mx1, __shfl_xor_sync(0xffffffffu, mx1, 1));
        mx1 = fmaxf(mx1, __shfl_xor_sync(0xffffffffu, mx1, 2));

        float mnew0 = fmaxf(mrun0, mx0);
        float mnew1 = fmaxf(mrun1, mx1);
        float corr0 = __expf(mrun0 - mnew0);
        float corr1 = __expf(mrun1 - mnew1);

        float ls0 = 0.f, ls1 = 0.f;
#pragma unroll
        for (int ni = 0; ni < 8; ni++) {
            float p0 = __expf(s[ni][0] - mnew0);
            float p1 = __expf(s[ni][1] - mnew0);
            float p2 = __expf(s[ni][2] - mnew1);
            float p3 = __expf(s[ni][3] - mnew1);
            ls0 += p0 + p1;
            ls1 += p2 + p3;
            int c = ni * 8 + tig * 2;
            Ps[m + g    ][c    ] = __uint_as_float(f2tf(p0));
            Ps[m + g    ][c + 1] = __uint_as_float(f2tf(p1));
            Ps[m + g + 8][c    ] = __uint_as_float(f2tf(p2));
            Ps[m + g + 8][c + 1] = __uint_as_float(f2tf(p3));
        }
        ls0 += __shfl_xor_sync(0xffffffffu, ls0, 1);
        ls0 += __shfl_xor_sync(0xffffffffu, ls0, 2);
        ls1 += __shfl_xor_sync(0xffffffffu, ls1, 1);
        ls1 += __shfl_xor_sync(0xffffffffu, ls1, 2);

        lrun0 = lrun0 * corr0 + ls0;
        lrun1 = lrun1 * corr1 + ls1;
        mrun0 = mnew0;
        mrun1 = mnew1;
#pragma unroll
        for (int ni = 0; ni < 8; ni++) {
            o[ni][0] *= corr0; o[ni][1] *= corr0;
            o[ni][2] *= corr1; o[ni][3] *= corr1;
        }
        __syncwarp();

        // ---- O += P @ V ----
#pragma unroll
        for (int kk = 0; kk < 8; kk++) {
            unsigned pf[4];
            pf[0] = __float_as_uint(Ps[m + g    ][kk * 8 + tig    ]);
            pf[1] = __float_as_uint(Ps[m + g + 8][kk * 8 + tig    ]);
            pf[2] = __float_as_uint(Ps[m + g    ][kk * 8 + tig + 4]);
            pf[3] = __float_as_uint(Ps[m + g + 8][kk * 8 + tig + 4]);
#pragma unroll
            for (int ni = 0; ni < 8; ni++) {
                unsigned vb[2];
                vb[0] = __float_as_uint(Vs[kk * 8 + tig    ][ni * 8 + g]);
                vb[1] = __float_as_uint(Vs[kk * 8 + tig + 4][ni * 8 + g]);
                mma_tf32(o[ni], pf, vb);
            }
        }
    }

    // ---- epilogue ----
    float inv0 = 1.f / lrun0;
    float inv1 = 1.f / lrun1;
#pragma unroll
    for (int ni = 0; ni < 8; ni++) {
        int col = ni * 8 + tig * 2;
        *(float2*)&O[baseO + (size_t)row0 * DMODEL + col] =
            make_float2(o[ni][0] * inv0, o[ni][1] * inv0);
        *(float2*)&O[baseO + (size_t)row1 * DMODEL + col] =
            make_float2(o[ni][2] * inv1, o[ni][3] * inv1);
    }
}

// ---------------------------------------------------------------------------
// Launch
// ---------------------------------------------------------------------------
extern "C" void kernel_launch(void* const* d_in, const int* in_sizes, int n_in,
                              void* d_out, int out_size) {
    const float* x      = (const float*)d_in[0];
    const float* wq     = (const float*)d_in[1];
    const float* wk     = (const float*)d_in[2];
    const float* wv     = (const float*)d_in[3];
    const float* w_proj = (const float*)d_in[4];
    const float* b_proj = (const float*)d_in[5];
    const float* w1     = (const float*)d_in[6];
    const float* b1     = (const float*)d_in[7];
    const float* w2     = (const float*)d_in[8];
    const float* b2     = (const float*)d_in[9];
    const float* g1     = (const float*)d_in[10];
    const float* be1    = (const float*)d_in[11];
    const float* g2     = (const float*)d_in[12];
    const float* be2    = (const float*)d_in[13];
    float* out = (float*)d_out;

    float *xn1, *qkv, *att, *x2, *xn2, *hb, *wqkv;
    cudaGetSymbolAddress((void**)&xn1,  g_xn1);
    cudaGetSymbolAddress((void**)&qkv,  g_qkv);
    cudaGetSymbolAddress((void**)&att,  g_att);
    cudaGetSymbolAddress((void**)&x2,   g_x2);
    cudaGetSymbolAddress((void**)&xn2,  g_xn2);
    cudaGetSymbolAddress((void**)&hb,   g_h);
    cudaGetSymbolAddress((void**)&wqkv, g_wqkv);

    // allow 56 KB dynamic smem on the GEMM instantiations
    cudaFuncSetAttribute(gemm_cp<0>, cudaFuncAttributeMaxDynamicSharedMemorySize, GEMM_SMEM_BYTES);
    cudaFuncSetAttribute(gemm_cp<3>, cudaFuncAttributeMaxDynamicSharedMemorySize, GEMM_SMEM_BYTES);
    cudaFuncSetAttribute(gemm_cp<5>, cudaFuncAttributeMaxDynamicSharedMemorySize, GEMM_SMEM_BYTES);

    // 1. LN1
    ln_kernel<<<NTOK, 256>>>(x, g1, be1, xn1);

    // 2. repack per-head weights into packed [D, 3072]
    repack_w<<<(DMODEL * DMODEL) / 256, 256>>>(wq, wqkv);
    repack_w<<<(DMODEL * DMODEL) / 256, 256>>>(wk, wqkv + DMODEL);
    repack_w<<<(DMODEL * DMODEL) / 256, 256>>>(wv, wqkv + 2 * DMODEL);

    // 3. fused QKV projection: [8192,1024] @ [1024,3072]
    gemm_cp<0><<<dim3(QKV3 / 128, NTOK / 128), 256, GEMM_SMEM_BYTES>>>(
        xn1, wqkv, nullptr, nullptr, qkv, NTOK, QKV3, DMODEL);

    // 4. attention (tf32 tensor cores)
    attn_mma<<<dim3(SEQ / 64, BATCH * NHEAD), 128>>>(qkv, att);

    // 5. output projection + bias + residual(xn1)
    dim3 gproj(DMODEL / 128, NTOK / 128);
    gemm_cp<5><<<gproj, 256, GEMM_SMEM_BYTES>>>(att, w_proj, b_proj, xn1, x2, NTOK, DMODEL, DMODEL);

    // 6. LN2
    ln_kernel<<<NTOK, 256>>>(x2, g2, be2, xn2);

    // 7. FFN up + bias + relu
    gemm_cp<3><<<dim3(DFF / 128, NTOK / 128), 256, GEMM_SMEM_BYTES>>>(
        xn2, w1, b1, nullptr, hb, NTOK, DFF, DMODEL);

    // 8. FFN down + bias + residual(xn2) -> out
    gemm_cp<5><<<gproj, 256, GEMM_SMEM_BYTES>>>(hb, w2, b2, xn2, out, NTOK, DMODEL, DFF);
}

// round 13
// speedup vs baseline: 7.7824x; 1.6744x over previous
#include <cuda_runtime.h>
#include <cuda_fp16.h>
#include <math.h>

// ---------------------------------------------------------------------------
// Problem constants
// ---------------------------------------------------------------------------
#define BATCH 8
#define SEQ 1024
#define DMODEL 1024
#define NHEAD 16
#define HDIM 64
#define DFF 4096
#define NTOK (BATCH * SEQ)          // 8192 rows
#define QKV3 (3 * DMODEL)           // 3072

// ---------------------------------------------------------------------------
// Scratch buffers (device globals: allocation-free)
// ---------------------------------------------------------------------------
__device__ __half g_xn1h[NTOK * DMODEL];
__device__ float  g_xn1f[NTOK * DMODEL];
__device__ __half g_qkvh[NTOK * QKV3];
__device__ __half g_atth[NTOK * DMODEL];
__device__ float  g_x2  [NTOK * DMODEL];
__device__ __half g_xn2h[NTOK * DMODEL];
__device__ float  g_xn2f[NTOK * DMODEL];
__device__ __half g_hbh [NTOK * DFF];
// k-pair-interleaved fp16 weights: word (kp, n) = {W[2kp][n], W[2kp+1][n]}
__device__ unsigned g_wqkv_i[(DMODEL / 2) * QKV3];
__device__ unsigned g_wproj_i[(DMODEL / 2) * DMODEL];
__device__ unsigned g_w1_i[(DMODEL / 2) * DFF];
__device__ unsigned g_w2_i[(DFF / 2) * DMODEL];

// ---------------------------------------------------------------------------
// helpers
// ---------------------------------------------------------------------------
__device__ __forceinline__ void mma_fp16(float* d, const unsigned* a, const unsigned* b) {
    asm volatile(
        "mma.sync.aligned.m16n8k16.row.col.f32.f16.f16.f32 "
        "{%0,%1,%2,%3}, {%4,%5,%6,%7}, {%8,%9}, {%0,%1,%2,%3};\n"
        : "+f"(d[0]), "+f"(d[1]), "+f"(d[2]), "+f"(d[3])
        : "r"(a[0]), "r"(a[1]), "r"(a[2]), "r"(a[3]), "r"(b[0]), "r"(b[1]));
}

__device__ __forceinline__ unsigned packh2(float lo, float hi) {
    __half2 h = __floats2half2_rn(lo, hi);
    return *(unsigned*)&h;
}

__device__ __forceinline__ void cpasync16(unsigned dst, const void* src) {
    asm volatile("cp.async.cg.shared.global [%0], [%1], 16;\n" :: "r"(dst), "l"(src));
}
#define CP_COMMIT() asm volatile("cp.async.commit_group;\n" ::: "memory")
#define CP_WAIT2()  asm volatile("cp.async.wait_group 2;\n" ::: "memory")

// ---------------------------------------------------------------------------
// LayerNorm: one block per row; writes fp32 AND fp16 outputs
// ---------------------------------------------------------------------------
__global__ void ln_kernel(const float* __restrict__ x, const float* __restrict__ g,
                          const float* __restrict__ b, float* __restrict__ yf,
                          __half* __restrict__ yh) {
    int row = blockIdx.x;
    int tid = threadIdx.x;
    const float* xr = x + (size_t)row * DMODEL;

    float v[4];
    float s = 0.f, s2 = 0.f;
#pragma unroll
    for (int i = 0; i < 4; i++) {
        v[i] = xr[tid + 256 * i];
        s  += v[i];
        s2 += v[i] * v[i];
    }
#pragma unroll
    for (int o = 16; o; o >>= 1) {
        s  += __shfl_xor_sync(0xffffffffu, s,  o);
        s2 += __shfl_xor_sync(0xffffffffu, s2, o);
    }
    __shared__ float ss[8], ss2[8];
    int w = tid >> 5, lane = tid & 31;
    if (lane == 0) { ss[w] = s; ss2[w] = s2; }
    __syncthreads();
    s = 0.f; s2 = 0.f;
#pragma unroll
    for (int i = 0; i < 8; i++) { s += ss[i]; s2 += ss2[i]; }

    float mean = s * (1.f / DMODEL);
    float var  = s2 * (1.f / DMODEL) - mean * mean;
    float rstd = rsqrtf(var + 1e-5f);
#pragma unroll
    for (int i = 0; i < 4; i++) {
        int c = tid + 256 * i;
        float val = (v[i] - mean) * rstd * g[c] + b[c];
        yf[(size_t)row * DMODEL + c] = val;
        yh[(size_t)row * DMODEL + c] = __float2half_rn(val);
    }
}

// ---------------------------------------------------------------------------
// Repack per-head QKV weight (H,D,E) -> interleaved fp16 words [D/2][3072]
// ---------------------------------------------------------------------------
__global__ void repack_qkv(const float* __restrict__ w, unsigned* __restrict__ wi,
                           int colOff) {
    int idx = blockIdx.x * 256 + threadIdx.x;    // over (D/2)*1024
    int kp = idx >> 10;
    int n  = idx & 1023;
    int h  = n >> 6;
    int e  = n & 63;
    float lo = w[(h << 16) + ((2 * kp)     << 6) + e];
    float hi = w[(h << 16) + ((2 * kp + 1) << 6) + e];
    wi[(size_t)kp * QKV3 + colOff + n] = packh2(lo, hi);
}

// ---------------------------------------------------------------------------
// Convert + interleave generic weight [K][N] fp32 -> words [K/2][N]
// grid: (N/256, K/2)
// ---------------------------------------------------------------------------
__global__ void conv_interleave(const float* __restrict__ w, unsigned* __restrict__ wi,
                                int N) {
    int n  = blockIdx.x * 256 + threadIdx.x;
    int kp = blockIdx.y;
    float lo = w[(size_t)(2 * kp) * N + n];
    float hi = w[(size_t)(2 * kp + 1) * N + n];
    wi[(size_t)kp * N + n] = packh2(lo, hi);
}

// ---------------------------------------------------------------------------
// FP16 tensor-core GEMM with 4-stage cp.async pipeline.
// C[M,N] = A[M,K] @ B[K,N]; A fp16 row-major; B interleaved words [K/2][N].
// 128x128x16 tiles, 256 threads, warp grid 2x4, warp tile 64x32,
// mma m16n8k16 fp16->fp32.
// SMEM (words): A stage [128][12] (8 kpair words + pad4), B stage [8][132].
//   a-frag banks: (12g+tig) distinct; b-frag banks: (4tig+g) distinct.
// EPI bits: 1 = +bias[col], 2 = relu, 4 = +res[row,col] (res fp32)
// OUT16: 1 -> write fp16 C16, 0 -> write fp32 C
// ---------------------------------------------------------------------------
#define STAGES 4
#define AW 12
#define BW 132
#define AS_WORDS (128 * AW)          // 1536
#define BS_WORDS (8 * BW)            // 1056
#define B_BASE_W (STAGES * AS_WORDS)
#define GEMM_SMEM_BYTES ((B_BASE_W + STAGES * BS_WORDS) * 4)   // 41472

template <int EPI, int OUT16>
__global__ __launch_bounds__(256, 2)
void gemm_h(const __half* __restrict__ A, const unsigned* __restrict__ Bi,
            const float* __restrict__ bias, const float* __restrict__ res,
            float* __restrict__ C, __half* __restrict__ C16,
            int M, int N, int K) {
    extern __shared__ unsigned smw[];
    const unsigned sbase = (unsigned)__cvta_generic_to_shared(smw);

    const int t  = threadIdx.x;
    const int bx = blockIdx.x;
    const int by = blockIdx.y;

    const int lane = t & 31;
    const int warp = t >> 5;
    const int wm   = warp & 1;
    const int wn   = warp >> 1;
    const int m0   = wm * 64;
    const int n0   = wn * 32;
    const int g    = lane >> 2;
    const int tig  = lane & 3;

    // loaders: A: thread -> (row m, 8-half group), B: thread -> (kp row, 4-word group)
    const int am  = t >> 1;
    const int ah  = (t & 1) * 8;         // half offset within row (16B)
    const int bkp = t >> 5;              // 0..7
    const int bn4 = (t & 31) * 4;        // word offset 0..124

    const __half*  Abase = A  + (size_t)(by * 128) * K;
    const unsigned* Bbase = Bi + bx * 128;

    float acc[4][4][4];
#pragma unroll
    for (int mi = 0; mi < 4; mi++)
#pragma unroll
        for (int ni = 0; ni < 4; ni++)
#pragma unroll
            for (int r = 0; r < 4; r++) acc[mi][ni][r] = 0.f;

    const int nTiles = K / 16;

    auto issue = [&](int st, int k0) {
        unsigned ad = sbase + (st * AS_WORDS + am * AW + (ah >> 1)) * 4;
        unsigned bd = sbase + (B_BASE_W + st * BS_WORDS + bkp * BW + bn4) * 4;
        cpasync16(ad, Abase + (size_t)am * K + k0 + ah);
        cpasync16(bd, Bbase + (size_t)(k0 / 2 + bkp) * N + bn4);
    };

    issue(0, 0);  CP_COMMIT();
    issue(1, 16); CP_COMMIT();
    issue(2, 32); CP_COMMIT();
    int lt = 3;

    for (int tt = 0; tt < nTiles; tt++) {
        CP_WAIT2();
        __syncthreads();

        if (lt < nTiles) issue(lt & (STAGES - 1), lt * 16);
        CP_COMMIT();
        lt++;

        const unsigned* As_ = smw + (tt & (STAGES - 1)) * AS_WORDS;
        const unsigned* Bs_ = smw + B_BASE_W + (tt & (STAGES - 1)) * BS_WORDS;

        unsigned af[4][4];
#pragma unroll
        for (int mi = 0; mi < 4; mi++) {
            int m = m0 + mi * 16 + g;
            af[mi][0] = As_[m * AW + tig];
            af[mi][1] = As_[(m + 8) * AW + tig];
            af[mi][2] = As_[m * AW + tig + 4];
            af[mi][3] = As_[(m + 8) * AW + tig + 4];
        }
        unsigned bf[4][2];
#pragma unroll
        for (int ni = 0; ni < 4; ni++) {
            int n = n0 + ni * 8 + g;
            bf[ni][0] = Bs_[tig * BW + n];
            bf[ni][1] = Bs_[(tig + 4) * BW + n];
        }
#pragma unroll
        for (int mi = 0; mi < 4; mi++)
#pragma unroll
            for (int ni = 0; ni < 4; ni++)
                mma_fp16(acc[mi][ni], af[mi], bf[ni]);

        __syncthreads();
    }

    // ---- epilogue ----
#pragma unroll
    for (int mi = 0; mi < 4; mi++) {
#pragma unroll
        for (int ni = 0; ni < 4; ni++) {
            int row = by * 128 + m0 + mi * 16 + g;
            int col = bx * 128 + n0 + ni * 8 + tig * 2;
            float v0 = acc[mi][ni][0];
            float v1 = acc[mi][ni][1];
            float v2 = acc[mi][ni][2];
            float v3 = acc[mi][ni][3];
            if (EPI & 1) {
                float bb0 = bias[col], bb1 = bias[col + 1];
                v0 += bb0; v1 += bb1; v2 += bb0; v3 += bb1;
            }
            if (EPI & 2) {
                v0 = fmaxf(v0, 0.f); v1 = fmaxf(v1, 0.f);
                v2 = fmaxf(v2, 0.f); v3 = fmaxf(v3, 0.f);
            }
            if (EPI & 4) {
                const float* r0 = res + (size_t)row * N + col;
                const float* r1 = r0 + (size_t)8 * N;
                v0 += r0[0]; v1 += r0[1]; v2 += r1[0]; v3 += r1[1];
            }
            if (OUT16) {
                *(unsigned*)(C16 + (size_t)row * N + col)       = packh2(v0, v1);
                *(unsigned*)(C16 + (size_t)(row + 8) * N + col) = packh2(v2, v3);
            } else {
                *(float2*)(C + (size_t)row * N + col)       = make_float2(v0, v1);
                *(float2*)(C + (size_t)(row + 8) * N + col) = make_float2(v2, v3);
            }
        }
    }
}

// ---------------------------------------------------------------------------
// FP16 tensor-core causal flash attention.
// Packed-QKV fp16 input (row stride 3072). Block = 128 threads (4 warps),
// 64 query rows of one (b,h); KV tiles of 64. m16n8k16 mma.
// SMEM word layouts (stride 68 words):
//   Ks[fp 0..31][key 0..63]: word = {K[key][2fp], K[key][2fp+1]}  (feat pairs)
//   Vs[kp 0..31][feat 0..63]: word = {V[2kp][feat], V[2kp+1][feat]} (key pairs)
// P matrix lives in registers only (packed via cvt.rn.f16x2).
// ---------------------------------------------------------------------------
#define TS 68

__global__ __launch_bounds__(128)
void attn_h(const __half* __restrict__ QKV, __half* __restrict__ O) {
    __shared__ unsigned Ks[32 * TS];
    __shared__ unsigned Vs[32 * TS];

    const int qb = blockIdx.x;
    const int bh = blockIdx.y;
    const int b  = bh >> 4;
    const int h  = bh & 15;
    const size_t baseQ = (size_t)b * SEQ * QKV3 + (size_t)h * HDIM;
    const size_t baseO = (size_t)b * SEQ * DMODEL + (size_t)h * HDIM;

    const int tid  = threadIdx.x;
    const int lane = tid & 31;
    const int warp = tid >> 5;
    const int g    = lane >> 2;
    const int tig  = lane & 3;
    const int m    = warp * 16;
    const int q0   = qb * 64;

    const int row0 = q0 + m + g;
    const int row1 = row0 + 8;

    // ---- Q fragments: direct 32-bit loads from packed-fp16 global ----
    unsigned qf[4][4];
    {
        const unsigned* qr0 = (const unsigned*)(QKV + baseQ + (size_t)row0 * QKV3);
        const unsigned* qr1 = (const unsigned*)(QKV + baseQ + (size_t)row1 * QKV3);
#pragma unroll
        for (int kk = 0; kk < 4; kk++) {
            qf[kk][0] = qr0[kk * 8 + tig];
            qf[kk][1] = qr1[kk * 8 + tig];
            qf[kk][2] = qr0[kk * 8 + tig + 4];
            qf[kk][3] = qr1[kk * 8 + tig + 4];
        }
    }

    float o[8][4];
#pragma unroll
    for (int ni = 0; ni < 8; ni++)
#pragma unroll
        for (int r = 0; r < 4; r++) o[ni][r] = 0.f;
    float mrun0 = -1e30f, mrun1 = -1e30f, lrun0 = 0.f, lrun1 = 0.f;

    const float scale = 0.125f;
    const unsigned qkvW = QKV3 / 2;      // row stride in words

    for (int kb = 0; kb <= qb; kb++) {
        __syncthreads();
        // ---- load K tile (transpose-pack: feature pairs x keys) ----
        {
            const unsigned* Kw = (const unsigned*)(QKV) +
                ((baseQ + DMODEL) >> 1) + (size_t)(kb * 64) * qkvW;
#pragma unroll
            for (int it = 0; it < 16; it++) {
                int i = it * 128 + tid;
                int f = (i >> 2) & 31;
                int r = (i & 3) + ((i >> 7) << 2);
                Ks[f * TS + r] = Kw[(size_t)r * qkvW + f];
            }
            // ---- load V tile (key-pair interleave) ----
            const unsigned* Vw = (const unsigned*)(QKV) +
                ((baseQ + 2 * DMODEL) >> 1) + (size_t)(kb * 64) * qkvW;
#pragma unroll
            for (int it = 0; it < 8; it++) {
                int i   = it * 128 + tid;
                int fp2 = i & 31;            // feature pair (2 words)
                int kp  = i >> 5;            // key pair
                unsigned w0 = Vw[(size_t)(2 * kp)     * qkvW + fp2];
                unsigned w1 = Vw[(size_t)(2 * kp + 1) * qkvW + fp2];
                Vs[kp * TS + 2 * fp2]     = __byte_perm(w0, w1, 0x5410);
                Vs[kp * TS + 2 * fp2 + 1] = __byte_perm(w0, w1, 0x7632);
            }
        }
        __syncthreads();

        // ---- S = Q @ K^T (k = features, n = keys) ----
        float s[8][4];
#pragma unroll
        for (int ni = 0; ni < 8; ni++)
#pragma unroll
            for (int r = 0; r < 4; r++) s[ni][r] = 0.f;
#pragma unroll
        for (int kk = 0; kk < 4; kk++) {
#pragma unroll
            for (int ni = 0; ni < 8; ni++) {
                unsigned bf[2];
                bf[0] = Ks[(kk * 8 + tig) * TS + ni * 8 + g];
                bf[1] = Ks[(kk * 8 + tig + 4) * TS + ni * 8 + g];
                mma_fp16(s[ni], qf[kk], bf);
            }
        }

        // ---- scale + causal mask ----
        if (kb == qb) {
#pragma unroll
            for (int ni = 0; ni < 8; ni++) {
                int c0 = kb * 64 + ni * 8 + tig * 2;
                int c1 = c0 + 1;
                s[ni][0] = (c0 <= row0) ? s[ni][0] * scale : -1e30f;
                s[ni][1] = (c1 <= row0) ? s[ni][1] * scale : -1e30f;
                s[ni][2] = (c0 <= row1) ? s[ni][2] * scale : -1e30f;
                s[ni][3] = (c1 <= row1) ? s[ni][3] * scale : -1e30f;
            }
        } else {
#pragma unroll
            for (int ni = 0; ni < 8; ni++) {
                s[ni][0] *= scale; s[ni][1] *= scale;
                s[ni][2] *= scale; s[ni][3] *= scale;
            }
        }

        // ---- online softmax ----
        float mx0 = -1e30f, mx1 = -1e30f;
#pragma unroll
        for (int ni = 0; ni < 8; ni++) {
            mx0 = fmaxf(mx0, fmaxf(s[ni][0], s[ni][1]));
            mx1 = fmaxf(mx1, fmaxf(s[ni][2], s[ni][3]));
        }
        mx0 = fmaxf(mx0, __shfl_xor_sync(0xffffffffu, mx0, 1));
        mx0 = fmaxf(mx0, __shfl_xor_sync(0xffffffffu, mx0, 2));
        mx1 = fmaxf(mx1, __shfl_xor_sync(0xffffffffu, mx1, 1));
        mx1 = fmaxf(mx1, __shfl_xor_sync(0xffffffffu, mx1, 2));

        float mnew0 = fmaxf(mrun0, mx0);
        float mnew1 = fmaxf(mrun1, mx1);
        float corr0 = __expf(mrun0 - mnew0);
        float corr1 = __expf(mrun1 - mnew1);

        float ls0 = 0.f, ls1 = 0.f;
#pragma unroll
        for (int ni = 0; ni < 8; ni++) {
            s[ni][0] = __expf(s[ni][0] - mnew0);
            s[ni][1] = __expf(s[ni][1] - mnew0);
            s[ni][2] = __expf(s[ni][2] - mnew1);
            s[ni][3] = __expf(s[ni][3] - mnew1);
            ls0 += s[ni][0] + s[ni][1];
            ls1 += s[ni][2] + s[ni][3];
        }
        ls0 += __shfl_xor_sync(0xffffffffu, ls0, 1);
        ls0 += __shfl_xor_sync(0xffffffffu, ls0, 2);
        ls1 += __shfl_xor_sync(0xffffffffu, ls1, 1);
        ls1 += __shfl_xor_sync(0xffffffffu, ls1, 2);

        lrun0 = lrun0 * corr0 + ls0;
        lrun1 = lrun1 * corr1 + ls1;
        mrun0 = mnew0;
        mrun1 = mnew1;
#pragma unroll
        for (int ni = 0; ni < 8; ni++) {
            o[ni][0] *= corr0; o[ni][1] *= corr0;
            o[ni][2] *= corr1; o[ni][3] *= corr1;
        }

        // ---- O += P @ V (P packed from registers; k = keys, n = features) ----
#pragma unroll
        for (int kk = 0; kk < 4; kk++) {
            unsigned pf[4];
            pf[0] = packh2(s[2 * kk][0],     s[2 * kk][1]);
            pf[1] = packh2(s[2 * kk][2],     s[2 * kk][3]);
            pf[2] = packh2(s[2 * kk + 1][0], s[2 * kk + 1][1]);
            pf[3] = packh2(s[2 * kk + 1][2], s[2 * kk + 1][3]);
#pragma unroll
            for (int ni = 0; ni < 8; ni++) {
                unsigned vb[2];
                vb[0] = Vs[(kk * 8 + tig) * TS + ni * 8 + g];
                vb[1] = Vs[(kk * 8 + tig + 4) * TS + ni * 8 + g];
                mma_fp16(o[ni], pf, vb);
            }
        }
    }

    // ---- epilogue: normalized fp16 output ----
    float inv0 = 1.f / lrun0;
    float inv1 = 1.f / lrun1;
#pragma unroll
    for (int ni = 0; ni < 8; ni++) {
        int col = ni * 8 + tig * 2;
        *(unsigned*)(O + baseO + (size_t)row0 * DMODEL + col) =
            packh2(o[ni][0] * inv0, o[ni][1] * inv0);
        *(unsigned*)(O + baseO + (size_t)row1 * DMODEL + col) =
            packh2(o[ni][2] * inv1, o[ni][3] * inv1);
    }
}

// ---------------------------------------------------------------------------
// Launch
// ---------------------------------------------------------------------------
extern "C" void kernel_launch(void* const* d_in, const int* in_sizes, int n_in,
                              void* d_out, int out_size) {
    const float* x      = (const float*)d_in[0];
    const float* wq     = (const float*)d_in[1];
    const float* wk     = (const float*)d_in[2];
    const float* wv     = (const float*)d_in[3];
    const float* w_proj = (const float*)d_in[4];
    const float* b_proj = (const float*)d_in[5];
    const float* w1     = (const float*)d_in[6];
    const float* b1     = (const float*)d_in[7];
    const float* w2     = (const float*)d_in[8];
    const float* b2     = (const float*)d_in[9];
    const float* g1     = (const float*)d_in[10];
    const float* be1    = (const float*)d_in[11];
    const float* g2     = (const float*)d_in[12];
    const float* be2    = (const float*)d_in[13];
    float* out = (float*)d_out;

    __half *xn1h, *qkvh, *atth, *xn2h, *hbh;
    float  *xn1f, *x2, *xn2f;
    unsigned *wqkvi, *wproji, *w1i, *w2i;
    cudaGetSymbolAddress((void**)&xn1h,  g_xn1h);
    cudaGetSymbolAddress((void**)&xn1f,  g_xn1f);
    cudaGetSymbolAddress((void**)&qkvh,  g_qkvh);
    cudaGetSymbolAddress((void**)&atth,  g_atth);
    cudaGetSymbolAddress((void**)&x2,    g_x2);
    cudaGetSymbolAddress((void**)&xn2h,  g_xn2h);
    cudaGetSymbolAddress((void**)&xn2f,  g_xn2f);
    cudaGetSymbolAddress((void**)&hbh,   g_hbh);
    cudaGetSymbolAddress((void**)&wqkvi, g_wqkv_i);
    cudaGetSymbolAddress((void**)&wproji,g_wproj_i);
    cudaGetSymbolAddress((void**)&w1i,   g_w1_i);
    cudaGetSymbolAddress((void**)&w2i,   g_w2_i);

    cudaFuncSetAttribute(gemm_h<0,1>, cudaFuncAttributeMaxDynamicSharedMemorySize, GEMM_SMEM_BYTES);
    cudaFuncSetAttribute(gemm_h<3,1>, cudaFuncAttributeMaxDynamicSharedMemorySize, GEMM_SMEM_BYTES);
    cudaFuncSetAttribute(gemm_h<5,0>, cudaFuncAttributeMaxDynamicSharedMemorySize, GEMM_SMEM_BYTES);

    // 1. LN1 (fp32 + fp16 outputs)
    ln_kernel<<<NTOK, 256>>>(x, g1, be1, xn1f, xn1h);

    // 2. weight conversion / interleave
    repack_qkv<<<(DMODEL / 2) * DMODEL / 256, 256>>>(wq, wqkvi, 0);
    repack_qkv<<<(DMODEL / 2) * DMODEL / 256, 256>>>(wk, wqkvi, DMODEL);
    repack_qkv<<<(DMODEL / 2) * DMODEL / 256, 256>>>(wv, wqkvi, 2 * DMODEL);
    conv_interleave<<<dim3(DMODEL / 256, DMODEL / 2), 256>>>(w_proj, wproji, DMODEL);
    conv_interleave<<<dim3(DFF / 256,    DMODEL / 2), 256>>>(w1, w1i, DFF);
    conv_interleave<<<dim3(DMODEL / 256, DFF / 2),    256>>>(w2, w2i, DMODEL);

    // 3. fused QKV projection -> fp16 packed qkv
    gemm_h<0,1><<<dim3(QKV3 / 128, NTOK / 128), 256, GEMM_SMEM_BYTES>>>(
        xn1h, wqkvi, nullptr, nullptr, nullptr, qkvh, NTOK, QKV3, DMODEL);

    // 4. attention -> fp16 att
    attn_h<<<dim3(SEQ / 64, BATCH * NHEAD), 128>>>(qkvh, atth);

    // 5. output projection + bias + residual(xn1 fp32) -> x2 fp32
    dim3 gproj(DMODEL / 128, NTOK / 128);
    gemm_h<5,0><<<gproj, 256, GEMM_SMEM_BYTES>>>(
        atth, wproji, b_proj, xn1f, x2, nullptr, NTOK, DMODEL, DMODEL);

    // 6. LN2
    ln_kernel<<<NTOK, 256>>>(x2, g2, be2, xn2f, xn2h);

    // 7. FFN up + bias + relu -> fp16 hb
    gemm_h<3,1><<<dim3(DFF / 128, NTOK / 128), 256, GEMM_SMEM_BYTES>>>(
        xn2h, w1i, b1, nullptr, nullptr, hbh, NTOK, DFF, DMODEL);

    // 8. FFN down + bias + residual(xn2 fp32) -> out fp32
    gemm_h<5,0><<<gproj, 256, GEMM_SMEM_BYTES>>>(
        hbh, w2i, b2, xn2f, out, nullptr, NTOK, DMODEL, DFF);
}

// round 16
// speedup vs baseline: 8.1970x; 1.0533x over previous
#include <cuda_runtime.h>
#include <cuda_fp16.h>
#include <math.h>

// ---------------------------------------------------------------------------
// Problem constants
// ---------------------------------------------------------------------------
#define BATCH 8
#define SEQ 1024
#define DMODEL 1024
#define NHEAD 16
#define HDIM 64
#define DFF 4096
#define NTOK (BATCH * SEQ)          // 8192 rows
#define QKV3 (3 * DMODEL)           // 3072

// ---------------------------------------------------------------------------
// Scratch buffers (device globals: allocation-free)
// ---------------------------------------------------------------------------
__device__ __half g_xn1h[NTOK * DMODEL];
__device__ float  g_xn1f[NTOK * DMODEL];
__device__ __half g_qkvh[NTOK * QKV3];
__device__ __half g_atth[NTOK * DMODEL];
__device__ float  g_x2  [NTOK * DMODEL];
__device__ __half g_xn2h[NTOK * DMODEL];
__device__ float  g_xn2f[NTOK * DMODEL];
__device__ __half g_hbh [NTOK * DFF];
// k-pair-interleaved fp16 weights: word (kp, n) = {W[2kp][n], W[2kp+1][n]}
__device__ unsigned g_wqkv_i[(DMODEL / 2) * QKV3];
__device__ unsigned g_wproj_i[(DMODEL / 2) * DMODEL];
__device__ unsigned g_w1_i[(DMODEL / 2) * DFF];
__device__ unsigned g_w2_i[(DFF / 2) * DMODEL];

// ---------------------------------------------------------------------------
// helpers
// ---------------------------------------------------------------------------
__device__ __forceinline__ void mma_fp16(float* d, const unsigned* a, const unsigned* b) {
    asm volatile(
        "mma.sync.aligned.m16n8k16.row.col.f32.f16.f16.f32 "
        "{%0,%1,%2,%3}, {%4,%5,%6,%7}, {%8,%9}, {%0,%1,%2,%3};\n"
        : "+f"(d[0]), "+f"(d[1]), "+f"(d[2]), "+f"(d[3])
        : "r"(a[0]), "r"(a[1]), "r"(a[2]), "r"(a[3]), "r"(b[0]), "r"(b[1]));
}

__device__ __forceinline__ unsigned packh2(float lo, float hi) {
    __half2 h = __floats2half2_rn(lo, hi);
    return *(unsigned*)&h;
}

__device__ __forceinline__ void cpasync16(unsigned dst, const void* src) {
    asm volatile("cp.async.cg.shared.global [%0], [%1], 16;\n" :: "r"(dst), "l"(src));
}
#define CP_COMMIT() asm volatile("cp.async.commit_group;\n" ::: "memory")
#define CP_WAIT2()  asm volatile("cp.async.wait_group 2;\n" ::: "memory")

// ---------------------------------------------------------------------------
// LayerNorm: one block per row; writes fp32 AND fp16 outputs
// ---------------------------------------------------------------------------
__global__ void ln_kernel(const float* __restrict__ x, const float* __restrict__ g,
                          const float* __restrict__ b, float* __restrict__ yf,
                          __half* __restrict__ yh) {
    int row = blockIdx.x;
    int tid = threadIdx.x;
    const float* xr = x + (size_t)row * DMODEL;

    float v[4];
    float s = 0.f, s2 = 0.f;
#pragma unroll
    for (int i = 0; i < 4; i++) {
        v[i] = xr[tid + 256 * i];
        s  += v[i];
        s2 += v[i] * v[i];
    }
#pragma unroll
    for (int o = 16; o; o >>= 1) {
        s  += __shfl_xor_sync(0xffffffffu, s,  o);
        s2 += __shfl_xor_sync(0xffffffffu, s2, o);
    }
    __shared__ float ss[8], ss2[8];
    int w = tid >> 5, lane = tid & 31;
    if (lane == 0) { ss[w] = s; ss2[w] = s2; }
    __syncthreads();
    s = 0.f; s2 = 0.f;
#pragma unroll
    for (int i = 0; i < 8; i++) { s += ss[i]; s2 += ss2[i]; }

    float mean = s * (1.f / DMODEL);
    float var  = s2 * (1.f / DMODEL) - mean * mean;
    float rstd = rsqrtf(var + 1e-5f);
#pragma unroll
    for (int i = 0; i < 4; i++) {
        int c = tid + 256 * i;
        float val = (v[i] - mean) * rstd * g[c] + b[c];
        yf[(size_t)row * DMODEL + c] = val;
        yh[(size_t)row * DMODEL + c] = __float2half_rn(val);
    }
}

// ---------------------------------------------------------------------------
// Fused weight conversion: all four weight sets -> interleaved fp16 words
// in ONE launch. Index space partitioned by region.
// ---------------------------------------------------------------------------
#define QKV_W  ((DMODEL / 2) * QKV3)     // 1,572,864
#define PROJ_W ((DMODEL / 2) * DMODEL)   //   524,288
#define W1_W   ((DMODEL / 2) * DFF)      // 2,097,152
#define W2_W   ((DFF / 2) * DMODEL)      // 2,097,152
#define CONV_TOTAL (QKV_W + PROJ_W + W1_W + W2_W)

__global__ void conv_all(const float* __restrict__ wq, const float* __restrict__ wk,
                         const float* __restrict__ wv, const float* __restrict__ wproj,
                         const float* __restrict__ w1, const float* __restrict__ w2,
                         unsigned* __restrict__ wqkvi, unsigned* __restrict__ wproji,
                         unsigned* __restrict__ w1i, unsigned* __restrict__ w2i) {
    int idx = blockIdx.x * 256 + threadIdx.x;
    if (idx < QKV_W) {
        int kp = idx / QKV3, n = idx % QKV3;
        int s = n >> 10, nn = n & 1023, h = nn >> 6, e = nn & 63;
        const float* w = (s == 0) ? wq : (s == 1) ? wk : wv;
        float lo = w[(h << 16) + ((2 * kp) << 6) + e];
        float hi = w[(h << 16) + ((2 * kp + 1) << 6) + e];
        wqkvi[idx] = packh2(lo, hi);
        return;
    }
    idx -= QKV_W;
    if (idx < PROJ_W) {
        int kp = idx >> 10, n = idx & 1023;
        wproji[idx] = packh2(wproj[(size_t)(2 * kp) * DMODEL + n],
                             wproj[(size_t)(2 * kp + 1) * DMODEL + n]);
        return;
    }
    idx -= PROJ_W;
    if (idx < W1_W) {
        int kp = idx >> 12, n = idx & 4095;
        w1i[idx] = packh2(w1[(size_t)(2 * kp) * DFF + n],
                          w1[(size_t)(2 * kp + 1) * DFF + n]);
        return;
    }
    idx -= W1_W;
    {
        int kp = idx >> 10, n = idx & 1023;
        w2i[idx] = packh2(w2[(size_t)(2 * kp) * DMODEL + n],
                          w2[(size_t)(2 * kp + 1) * DMODEL + n]);
    }
}

// ---------------------------------------------------------------------------
// FP16 tensor-core GEMM, CTA tile 128x256, warp tile 64x64 (2x4 warp grid),
// 256 threads, 4-stage cp.async ring, ONE sync per k16 iteration.
// A fp16 row-major [M][K]; B interleaved words [K/2][N].
// SMEM (words per stage): A [128][12] (8 kpair words + pad4), B [8][264].
//   a-frag banks (12g+tig mod 32) distinct; b-frag banks (8tig+g) distinct.
// EPI bits: 1 = +bias[col], 2 = relu, 4 = +res[row,col] (res fp32)
// OUT16: 1 -> write fp16 C16, 0 -> write fp32 C
// ---------------------------------------------------------------------------
#define STAGES 4
#define AW 12
#define BW 264
#define AS_WORDS (128 * AW)          // 1536
#define BS_WORDS (8 * BW)            // 2112
#define STG_WORDS (AS_WORDS + BS_WORDS)
#define GEMM_SMEM_BYTES (STAGES * STG_WORDS * 4)   // 58368

template <int EPI, int OUT16>
__global__ __launch_bounds__(256, 1)
void gemm_h(const __half* __restrict__ A, const unsigned* __restrict__ Bi,
            const float* __restrict__ bias, const float* __restrict__ res,
            float* __restrict__ C, __half* __restrict__ C16,
            int M, int N, int K) {
    extern __shared__ unsigned smw[];
    const unsigned sbase = (unsigned)__cvta_generic_to_shared(smw);

    const int t  = threadIdx.x;
    const int bx = blockIdx.x;
    const int by = blockIdx.y;

    const int lane = t & 31;
    const int warp = t >> 5;
    const int wm   = warp >> 2;          // 2 warps along M
    const int wn   = warp & 3;           // 4 warps along N
    const int m0   = wm * 64;
    const int n0   = wn * 64;
    const int g    = lane >> 2;
    const int tig  = lane & 3;

    // loaders: A 256 chunks (1/thread), B 512 chunks (2/thread)
    const int ar  = t >> 1;
    const int aw4 = (t & 1) * 4;         // word offset within row (0 or 4)
    const int bkp0 = t >> 6,          bw0 = (t & 63) * 4;
    const int bkp1 = (t + 256) >> 6,  bw1 = ((t + 256) & 63) * 4;

    const __half*   Abase = A  + (size_t)(by * 128) * K;
    const unsigned* Bbase = Bi + bx * 256;

    float acc[4][8][4];
#pragma unroll
    for (int mi = 0; mi < 4; mi++)
#pragma unroll
        for (int ni = 0; ni < 8; ni++)
#pragma unroll
            for (int r = 0; r < 4; r++) acc[mi][ni][r] = 0.f;

    const int nTiles = K / 16;

    auto issue = [&](int st, int k0) {
        unsigned ab = sbase + (st * STG_WORDS) * 4;
        unsigned bb = ab + AS_WORDS * 4;
        cpasync16(ab + (ar * AW + aw4) * 4, Abase + (size_t)ar * K + k0 + aw4 * 2);
        cpasync16(bb + (bkp0 * BW + bw0) * 4, Bbase + (size_t)(k0 / 2 + bkp0) * N + bw0);
        cpasync16(bb + (bkp1 * BW + bw1) * 4, Bbase + (size_t)(k0 / 2 + bkp1) * N + bw1);
        CP_COMMIT();
    };

    issue(0, 0);
    issue(1, 16);
    issue(2, 32);
    int lt = 3;

    for (int tt = 0; tt < nTiles; tt++) {
        CP_WAIT2();                // group(tt) complete (2 newer may be in flight)
        __syncthreads();           // all reads of stage (tt-1)%4 done; stage tt visible

        if (lt < nTiles) issue(lt & (STAGES - 1), lt * 16);
        else CP_COMMIT();
        lt++;

        const unsigned* As_ = smw + (tt & (STAGES - 1)) * STG_WORDS;
        const unsigned* Bs_ = As_ + AS_WORDS;

        unsigned af[4][4];
#pragma unroll
        for (int mi = 0; mi < 4; mi++) {
            int m = m0 + mi * 16 + g;
            af[mi][0] = As_[m * AW + tig];
            af[mi][1] = As_[(m + 8) * AW + tig];
            af[mi][2] = As_[m * AW + tig + 4];
            af[mi][3] = As_[(m + 8) * AW + tig + 4];
        }
        unsigned bf[8][2];
#pragma unroll
        for (int ni = 0; ni < 8; ni++) {
            int n = n0 + ni * 8 + g;
            bf[ni][0] = Bs_[tig * BW + n];
            bf[ni][1] = Bs_[(tig + 4) * BW + n];
        }
#pragma unroll
        for (int mi = 0; mi < 4; mi++)
#pragma unroll
            for (int ni = 0; ni < 8; ni++)
                mma_fp16(acc[mi][ni], af[mi], bf[ni]);
    }

    // ---- epilogue ----
#pragma unroll
    for (int mi = 0; mi < 4; mi++) {
#pragma unroll
        for (int ni = 0; ni < 8; ni++) {
            int row = by * 128 + m0 + mi * 16 + g;
            int col = bx * 256 + n0 + ni * 8 + tig * 2;
            float v0 = acc[mi][ni][0];
            float v1 = acc[mi][ni][1];
            float v2 = acc[mi][ni][2];
            float v3 = acc[mi][ni][3];
            if (EPI & 1) {
                float bb0 = bias[col], bb1 = bias[col + 1];
                v0 += bb0; v1 += bb1; v2 += bb0; v3 += bb1;
            }
            if (EPI & 2) {
                v0 = fmaxf(v0, 0.f); v1 = fmaxf(v1, 0.f);
                v2 = fmaxf(v2, 0.f); v3 = fmaxf(v3, 0.f);
            }
            if (EPI & 4) {
                const float* r0 = res + (size_t)row * N + col;
                const float* r1 = r0 + (size_t)8 * N;
                v0 += r0[0]; v1 += r0[1]; v2 += r1[0]; v3 += r1[1];
            }
            if (OUT16) {
                *(unsigned*)(C16 + (size_t)row * N + col)       = packh2(v0, v1);
                *(unsigned*)(C16 + (size_t)(row + 8) * N + col) = packh2(v2, v3);
            } else {
                *(float2*)(C + (size_t)row * N + col)       = make_float2(v0, v1);
                *(float2*)(C + (size_t)(row + 8) * N + col) = make_float2(v2, v3);
            }
        }
    }
}

// ---------------------------------------------------------------------------
// FP16 tensor-core causal flash attention (unchanged from R6 — proven).
// ---------------------------------------------------------------------------
#define TS 68

__global__ __launch_bounds__(128)
void attn_h(const __half* __restrict__ QKV, __half* __restrict__ O) {
    __shared__ unsigned Ks[32 * TS];
    __shared__ unsigned Vs[32 * TS];

    const int qb = blockIdx.x;
    const int bh = blockIdx.y;
    const int b  = bh >> 4;
    const int h  = bh & 15;
    const size_t baseQ = (size_t)b * SEQ * QKV3 + (size_t)h * HDIM;
    const size_t baseO = (size_t)b * SEQ * DMODEL + (size_t)h * HDIM;

    const int tid  = threadIdx.x;
    const int lane = tid & 31;
    const int warp = tid >> 5;
    const int g    = lane >> 2;
    const int tig  = lane & 3;
    const int m    = warp * 16;
    const int q0   = qb * 64;

    const int row0 = q0 + m + g;
    const int row1 = row0 + 8;

    unsigned qf[4][4];
    {
        const unsigned* qr0 = (const unsigned*)(QKV + baseQ + (size_t)row0 * QKV3);
        const unsigned* qr1 = (const unsigned*)(QKV + baseQ + (size_t)row1 * QKV3);
#pragma unroll
        for (int kk = 0; kk < 4; kk++) {
            qf[kk][0] = qr0[kk * 8 + tig];
            qf[kk][1] = qr1[kk * 8 + tig];
            qf[kk][2] = qr0[kk * 8 + tig + 4];
            qf[kk][3] = qr1[kk * 8 + tig + 4];
        }
    }

    float o[8][4];
#pragma unroll
    for (int ni = 0; ni < 8; ni++)
#pragma unroll
        for (int r = 0; r < 4; r++) o[ni][r] = 0.f;
    float mrun0 = -1e30f, mrun1 = -1e30f, lrun0 = 0.f, lrun1 = 0.f;

    const float scale = 0.125f;
    const unsigned qkvW = QKV3 / 2;

    for (int kb = 0; kb <= qb; kb++) {
        __syncthreads();
        {
            const unsigned* Kw = (const unsigned*)(QKV) +
                ((baseQ + DMODEL) >> 1) + (size_t)(kb * 64) * qkvW;
#pragma unroll
            for (int it = 0; it < 16; it++) {
                int i = it * 128 + tid;
                int f = (i >> 2) & 31;
                int r = (i & 3) + ((i >> 7) << 2);
                Ks[f * TS + r] = Kw[(size_t)r * qkvW + f];
            }
            const unsigned* Vw = (const unsigned*)(QKV) +
                ((baseQ + 2 * DMODEL) >> 1) + (size_t)(kb * 64) * qkvW;
#pragma unroll
            for (int it = 0; it < 8; it++) {
                int i   = it * 128 + tid;
                int fp2 = i & 31;
                int kp  = i >> 5;
                unsigned w0 = Vw[(size_t)(2 * kp)     * qkvW + fp2];
                unsigned w1 = Vw[(size_t)(2 * kp + 1) * qkvW + fp2];
                Vs[kp * TS + 2 * fp2]     = __byte_perm(w0, w1, 0x5410);
                Vs[kp * TS + 2 * fp2 + 1] = __byte_perm(w0, w1, 0x7632);
            }
        }
        __syncthreads();

        float s[8][4];
#pragma unroll
        for (int ni = 0; ni < 8; ni++)
#pragma unroll
            for (int r = 0; r < 4; r++) s[ni][r] = 0.f;
#pragma unroll
        for (int kk = 0; kk < 4; kk++) {
#pragma unroll
            for (int ni = 0; ni < 8; ni++) {
                unsigned bf[2];
                bf[0] = Ks[(kk * 8 + tig) * TS + ni * 8 + g];
                bf[1] = Ks[(kk * 8 + tig + 4) * TS + ni * 8 + g];
                mma_fp16(s[ni], qf[kk], bf);
            }
        }

        if (kb == qb) {
#pragma unroll
            for (int ni = 0; ni < 8; ni++) {
                int c0 = kb * 64 + ni * 8 + tig * 2;
                int c1 = c0 + 1;
                s[ni][0] = (c0 <= row0) ? s[ni][0] * scale : -1e30f;
                s[ni][1] = (c1 <= row0) ? s[ni][1] * scale : -1e30f;
                s[ni][2] = (c0 <= row1) ? s[ni][2] * scale : -1e30f;
                s[ni][3] = (c1 <= row1) ? s[ni][3] * scale : -1e30f;
            }
        } else {
#pragma unroll
            for (int ni = 0; ni < 8; ni++) {
                s[ni][0] *= scale; s[ni][1] *= scale;
                s[ni][2] *= scale; s[ni][3] *= scale;
            }
        }

        float mx0 = -1e30f, mx1 = -1e30f;
#pragma unroll
        for (int ni = 0; ni < 8; ni++) {
            mx0 = fmaxf(mx0, fmaxf(s[ni][0], s[ni][1]));
            mx1 = fmaxf(mx1, fmaxf(s[ni][2], s[ni][3]));
        }
        mx0 = fmaxf(mx0, __shfl_xor_sync(0xffffffffu, mx0, 1));
        mx0 = fmaxf(mx0, __shfl_xor_sync(0xffffffffu, mx0, 2));
        mx1 = fmaxf(mx1, __shfl_xor_sync(0xffffffffu, mx1, 1));
        mx1 = fmaxf(mx1, __shfl_xor_sync(0xffffffffu, mx1, 2));

        float mnew0 = fmaxf(mrun0, mx0);
        float mnew1 = fmaxf(mrun1, mx1);
        float corr0 = __expf(mrun0 - mnew0);
        float corr1 = __expf(mrun1 - mnew1);

        float ls0 = 0.f, ls1 = 0.f;
#pragma unroll
        for (int ni = 0; ni < 8; ni++) {
            s[ni][0] = __expf(s[ni][0] - mnew0);
            s[ni][1] = __expf(s[ni][1] - mnew0);
            s[ni][2] = __expf(s[ni][2] - mnew1);
            s[ni][3] = __expf(s[ni][3] - mnew1);
            ls0 += s[ni][0] + s[ni][1];
            ls1 += s[ni][2] + s[ni][3];
        }
        ls0 += __shfl_xor_sync(0xffffffffu, ls0, 1);
        ls0 += __shfl_xor_sync(0xffffffffu, ls0, 2);
        ls1 += __shfl_xor_sync(0xffffffffu, ls1, 1);
        ls1 += __shfl_xor_sync(0xffffffffu, ls1, 2);

        lrun0 = lrun0 * corr0 + ls0;
        lrun1 = lrun1 * corr1 + ls1;
        mrun0 = mnew0;
        mrun1 = mnew1;
#pragma unroll
        for (int ni = 0; ni < 8; ni++) {
            o[ni][0] *= corr0; o[ni][1] *= corr0;
            o[ni][2] *= corr1; o[ni][3] *= corr1;
        }

#pragma unroll
        for (int kk = 0; kk < 4; kk++) {
            unsigned pf[4];
            pf[0] = packh2(s[2 * kk][0],     s[2 * kk][1]);
            pf[1] = packh2(s[2 * kk][2],     s[2 * kk][3]);
            pf[2] = packh2(s[2 * kk + 1][0], s[2 * kk + 1][1]);
            pf[3] = packh2(s[2 * kk + 1][2], s[2 * kk + 1][3]);
#pragma unroll
            for (int ni = 0; ni < 8; ni++) {
                unsigned vb[2];
                vb[0] = Vs[(kk * 8 + tig) * TS + ni * 8 + g];
                vb[1] = Vs[(kk * 8 + tig + 4) * TS + ni * 8 + g];
                mma_fp16(o[ni], pf, vb);
            }
        }
    }

    float inv0 = 1.f / lrun0;
    float inv1 = 1.f / lrun1;
#pragma unroll
    for (int ni = 0; ni < 8; ni++) {
        int col = ni * 8 + tig * 2;
        *(unsigned*)(O + baseO + (size_t)row0 * DMODEL + col) =
            packh2(o[ni][0] * inv0, o[ni][1] * inv0);
        *(unsigned*)(O + baseO + (size_t)row1 * DMODEL + col) =
            packh2(o[ni][2] * inv1, o[ni][3] * inv1);
    }
}

// ---------------------------------------------------------------------------
// Launch
// ---------------------------------------------------------------------------
extern "C" void kernel_launch(void* const* d_in, const int* in_sizes, int n_in,
                              void* d_out, int out_size) {
    const float* x      = (const float*)d_in[0];
    const float* wq     = (const float*)d_in[1];
    const float* wk     = (const float*)d_in[2];
    const float* wv     = (const float*)d_in[3];
    const float* w_proj = (const float*)d_in[4];
    const float* b_proj = (const float*)d_in[5];
    const float* w1     = (const float*)d_in[6];
    const float* b1     = (const float*)d_in[7];
    const float* w2     = (const float*)d_in[8];
    const float* b2     = (const float*)d_in[9];
    const float* g1     = (const float*)d_in[10];
    const float* be1    = (const float*)d_in[11];
    const float* g2     = (const float*)d_in[12];
    const float* be2    = (const float*)d_in[13];
    float* out = (float*)d_out;

    __half *xn1h, *qkvh, *atth, *xn2h, *hbh;
    float  *xn1f, *x2, *xn2f;
    unsigned *wqkvi, *wproji, *w1i, *w2i;
    cudaGetSymbolAddress((void**)&xn1h,  g_xn1h);
    cudaGetSymbolAddress((void**)&xn1f,  g_xn1f);
    cudaGetSymbolAddress((void**)&qkvh,  g_qkvh);
    cudaGetSymbolAddress((void**)&atth,  g_atth);
    cudaGetSymbolAddress((void**)&x2,    g_x2);
    cudaGetSymbolAddress((void**)&xn2h,  g_xn2h);
    cudaGetSymbolAddress((void**)&xn2f,  g_xn2f);
    cudaGetSymbolAddress((void**)&hbh,   g_hbh);
    cudaGetSymbolAddress((void**)&wqkvi, g_wqkv_i);
    cudaGetSymbolAddress((void**)&wproji,g_wproj_i);
    cudaGetSymbolAddress((void**)&w1i,   g_w1_i);
    cudaGetSymbolAddress((void**)&w2i,   g_w2_i);

    cudaFuncSetAttribute(gemm_h<0,1>, cudaFuncAttributeMaxDynamicSharedMemorySize, GEMM_SMEM_BYTES);
    cudaFuncSetAttribute(gemm_h<3,1>, cudaFuncAttributeMaxDynamicSharedMemorySize, GEMM_SMEM_BYTES);
    cudaFuncSetAttribute(gemm_h<5,0>, cudaFuncAttributeMaxDynamicSharedMemorySize, GEMM_SMEM_BYTES);

    // 1. LN1 (fp32 + fp16 outputs)
    ln_kernel<<<NTOK, 256>>>(x, g1, be1, xn1f, xn1h);

    // 2. all weight conversions, one launch
    conv_all<<<CONV_TOTAL / 256, 256>>>(wq, wk, wv, w_proj, w1, w2,
                                        wqkvi, wproji, w1i, w2i);

    // 3. fused QKV projection -> fp16 packed qkv
    gemm_h<0,1><<<dim3(QKV3 / 256, NTOK / 128), 256, GEMM_SMEM_BYTES>>>(
        xn1h, wqkvi, nullptr, nullptr, nullptr, qkvh, NTOK, QKV3, DMODEL);

    // 4. attention -> fp16 att
    attn_h<<<dim3(SEQ / 64, BATCH * NHEAD), 128>>>(qkvh, atth);

    // 5. output projection + bias + residual(xn1 fp32) -> x2 fp32
    gemm_h<5,0><<<dim3(DMODEL / 256, NTOK / 128), 256, GEMM_SMEM_BYTES>>>(
        atth, wproji, b_proj, xn1f, x2, nullptr, NTOK, DMODEL, DMODEL);

    // 6. LN2
    ln_kernel<<<NTOK, 256>>>(x2, g2, be2, xn2f, xn2h);

    // 7. FFN up + bias + relu -> fp16 hb
    gemm_h<3,1><<<dim3(DFF / 256, NTOK / 128), 256, GEMM_SMEM_BYTES>>>(
        xn2h, w1i, b1, nullptr, nullptr, hbh, NTOK, DFF, DMODEL);

    // 8. FFN down + bias + residual(xn2 fp32) -> out fp32
    gemm_h<5,0><<<dim3(DMODEL / 256, NTOK / 128), 256, GEMM_SMEM_BYTES>>>(
        hbh, w2i, b2, xn2f, out, nullptr, NTOK, DMODEL, DFF);
}